// round 14
// baseline (speedup 1.0000x reference)
#include <cuda_runtime.h>
#include <cuda_bf16.h>
#include <cstdint>

#define B_DIM  2048
#define NVIS   2048
#define NHID   1024
#define NCLASS 64
#define PTHRESH 14.0f

// ---------------------------------------------------------------------------
// Static device scratch
// ---------------------------------------------------------------------------
__device__ float g_pre[B_DIM * NHID];                 // 8 MB
__device__ __nv_bfloat16 g_vh[B_DIM * NVIS];          // 8 MB
__device__ __nv_bfloat16 g_vm[B_DIM * NVIS];          // 8 MB
__device__ __nv_bfloat16 g_wh[NHID * NVIS];           // 4 MB (W^T limbs, [n][k])
__device__ __nv_bfloat16 g_wm[NHID * NVIS];           // 4 MB
__device__ __nv_bfloat16 g_m1[B_DIM * NHID];          // 4 MB  1[p>14]
__device__ __nv_bfloat16 g_a2[B_DIM * NHID];          // 4 MB  e^-p (p>14)
__device__ __nv_bfloat16 g_a3[B_DIM * NHID];          // 4 MB  e^p  (p<-14)
__device__ __nv_bfloat16 g_uh[NCLASS * NHID];         // U limbs [y][j]
__device__ __nv_bfloat16 g_um[NCLASS * NHID];
__device__ __nv_bfloat16 g_ul[NCLASS * NHID];
__device__ __nv_bfloat16 g_emu[NCLASS * NHID];        // e^-u
__device__ __nv_bfloat16 g_epu[NCLASS * NHID];        // e^+u
__device__ float g_G[4 * B_DIM * NCLASS];             // split-K mask-GEMM parts
__device__ float g_Fp[4 * B_DIM * NCLASS];            // split-j fenergy partials

__device__ __forceinline__ uint32_t smem_u32(const void* p) {
    uint32_t a;
    asm("{ .reg .u64 t; cvta.to.shared.u64 t, %1; cvt.u32.u64 %0, t; }" : "=r"(a) : "l"(p));
    return a;
}

// ---------------------------------------------------------------------------
// K0: fused split kernel: v limbs, W^T limbs, U 3-limb + e^{±u} copies
// ---------------------------------------------------------------------------
__global__ __launch_bounds__(256) void split_kernel(const float* __restrict__ v,
                                                    const float* __restrict__ W,
                                                    const float* __restrict__ U) {
    if (blockIdx.x < 1024) {
        const int base = blockIdx.x * 1024 + threadIdx.x;   // float4 index
        float4 x[4];
#pragma unroll
        for (int r = 0; r < 4; r++)
            x[r] = *(const float4*)(v + (size_t)(base + r * 256) * 4);
#pragma unroll
        for (int r = 0; r < 4; r++) {
            float xs[4] = {x[r].x, x[r].y, x[r].z, x[r].w};
            __nv_bfloat16 hb[4], mb[4];
#pragma unroll
            for (int i = 0; i < 4; i++) {
                hb[i] = __float2bfloat16(xs[i]);
                mb[i] = __float2bfloat16(xs[i] - __bfloat162float(hb[i]));
            }
            size_t o = (size_t)(base + r * 256) * 4;
            *(uint2*)(g_vh + o) = *(uint2*)hb;
            *(uint2*)(g_vm + o) = *(uint2*)mb;
        }
    } else if (blockIdx.x < 3072) {
        __shared__ float s[32][33];
        int bid = blockIdx.x - 1024;
        int nb = (bid & 31) * 32;
        int kb = (bid >> 5) * 32;
        int tx = threadIdx.x & 31;
        int ty = threadIdx.x >> 5;
        float w[4];
#pragma unroll
        for (int i = 0; i < 4; i++)
            w[i] = W[(size_t)(kb + ty + i * 8) * NHID + nb + tx];
#pragma unroll
        for (int i = 0; i < 4; i++)
            s[ty + i * 8][tx] = w[i];
        __syncthreads();
#pragma unroll
        for (int i = 0; i < 4; i++) {
            int n = ty + i * 8;
            float x = s[tx][n];
            __nv_bfloat16 h = __float2bfloat16(x);
            __nv_bfloat16 m = __float2bfloat16(x - __bfloat162float(h));
            size_t o = (size_t)(nb + n) * NVIS + kb + tx;
            g_wh[o] = h; g_wm[o] = m;
        }
    } else {
        // U: 3-limb split + e^{-u}, e^{+u}
        const int base = (blockIdx.x - 3072) * 1024 + threadIdx.x;
#pragma unroll
        for (int r = 0; r < 4; r++) {
            int idx = base + r * 256;
            float4 x4 = *(const float4*)(U + (size_t)idx * 4);
            float xs[4] = {x4.x, x4.y, x4.z, x4.w};
            __nv_bfloat16 hb[4], mb[4], lb[4], eb[4], pb[4];
#pragma unroll
            for (int i = 0; i < 4; i++) {
                hb[i] = __float2bfloat16(xs[i]);
                float r1 = xs[i] - __bfloat162float(hb[i]);
                mb[i] = __float2bfloat16(r1);
                lb[i] = __float2bfloat16(r1 - __bfloat162float(mb[i]));
                eb[i] = __float2bfloat16(__expf(-xs[i]));
                pb[i] = __float2bfloat16(__expf(xs[i]));
            }
            size_t o = (size_t)idx * 4;
            *(uint2*)(g_uh + o) = *(uint2*)hb;
            *(uint2*)(g_um + o) = *(uint2*)mb;
            *(uint2*)(g_ul + o) = *(uint2*)lb;
            *(uint2*)(g_emu + o) = *(uint2*)eb;
            *(uint2*)(g_epu + o) = *(uint2*)pb;
        }
    }
}

// ---------------------------------------------------------------------------
// Shared GEMM macros
// ---------------------------------------------------------------------------
#define CP_ASYNC(dst, src) \
    asm volatile("cp.async.cg.shared.global [%0], [%1], 16;" :: "r"(dst), "l"(src))
#define CP_COMMIT() asm volatile("cp.async.commit_group;" ::: "memory")
#define CP_WAIT(n)  asm volatile("cp.async.wait_group %0;" :: "n"(n) : "memory")

#define LDSM_X4(r0, r1, r2, r3, a) \
    asm volatile("ldmatrix.sync.aligned.m8n8.x4.shared.b16 {%0,%1,%2,%3}, [%4];" \
        : "=r"(r0), "=r"(r1), "=r"(r2), "=r"(r3) : "r"(a))

#define MMA16816(c0, c1, c2, c3, a0, a1, a2, a3, b0, b1) \
    asm volatile("mma.sync.aligned.m16n8k16.row.col.f32.bf16.bf16.f32 " \
        "{%0,%1,%2,%3}, {%4,%5,%6,%7}, {%8,%9}, {%0,%1,%2,%3};" \
        : "+f"(c0), "+f"(c1), "+f"(c2), "+f"(c3) \
        : "r"(a0), "r"(a1), "r"(a2), "r"(a3), "r"(b0), "r"(b1))

// ---------------------------------------------------------------------------
// K1: pre = v @ W + c  (proven config) + m1/a2/a3 writes in epilogue
// ---------------------------------------------------------------------------
#define KC        64
#define ROWB      144
#define TILEB     (128 * ROWB)
#define BUFB      (4 * TILEB)
#define STAGES    3
#define GEMM_SMEM (STAGES * BUFB)        // 221184

__global__ __launch_bounds__(256, 1) void gemm_mma_kernel(const float* __restrict__ cvec) {
    extern __shared__ char smem[];
    const int tid  = threadIdx.x;
    const int wid  = tid >> 5;
    const int lane = tid & 31;
    const int block_row = blockIdx.y * 128;
    const int block_col = blockIdx.x * 128;

    const __nv_bfloat16* srcs[4] = {g_vh, g_vm, g_wh, g_wm};

    auto load_chunk = [&](int k0, int stage) {
        char* bufp = smem + stage * BUFB;
#pragma unroll
        for (int t = 0; t < 4; t++) {
            const int row0 = (t < 2) ? block_row : block_col;
            const __nv_bfloat16* src = srcs[t];
#pragma unroll
            for (int i = 0; i < 4; i++) {
                int idx = i * 256 + tid;
                int r = idx >> 3;
                int c = idx & 7;
                const void* g = src + (size_t)(row0 + r) * NVIS + k0 + c * 8;
                uint32_t d = smem_u32(bufp + t * TILEB + r * ROWB + c * 16);
                CP_ASYNC(d, g);
            }
        }
    };

    const int m_off = (wid >> 2) * 64;
    const int n_off = (wid & 3) * 32;

    const uint32_t a_lane = (uint32_t)(m_off + (lane & 15)) * ROWB + (lane >> 4) * 16;
    const uint32_t b_lane = (uint32_t)(n_off + ((lane >> 4) & 1) * 8 + (lane & 7)) * ROWB
                          + ((lane >> 3) & 1) * 16;

    float acc[4][4][4];
#pragma unroll
    for (int mi = 0; mi < 4; mi++)
#pragma unroll
        for (int ni = 0; ni < 4; ni++)
#pragma unroll
            for (int q = 0; q < 4; q++) acc[mi][ni][q] = 0.0f;

    const int NCHUNK = NVIS / KC;

    load_chunk(0, 0); CP_COMMIT();
    load_chunk(KC, 1); CP_COMMIT();

    for (int ch = 0; ch < NCHUNK; ch++) {
        if (ch + 2 < NCHUNK) { load_chunk((ch + 2) * KC, (ch + 2) % STAGES); CP_COMMIT(); }
        if (ch + 2 < NCHUNK)      { CP_WAIT(2); }
        else if (ch + 1 < NCHUNK) { CP_WAIT(1); }
        else                      { CP_WAIT(0); }
        __syncthreads();

        const char* bufp = smem + (ch % STAGES) * BUFB;
        const uint32_t a_base0 = smem_u32(bufp) + a_lane;
        const uint32_t a_base1 = a_base0 + TILEB;
        const uint32_t b_base0 = smem_u32(bufp + 2 * TILEB) + b_lane;
        const uint32_t b_base1 = b_base0 + TILEB;

#pragma unroll
        for (int ks = 0; ks < KC / 16; ks++) {
            uint32_t Af[2][4][4];
            uint32_t Bf[2][4][2];
#pragma unroll
            for (int mi = 0; mi < 4; mi++) {
                LDSM_X4(Af[0][mi][0], Af[0][mi][1], Af[0][mi][2], Af[0][mi][3],
                        a_base0 + (uint32_t)mi * 16 * ROWB + ks * 32);
                LDSM_X4(Af[1][mi][0], Af[1][mi][1], Af[1][mi][2], Af[1][mi][3],
                        a_base1 + (uint32_t)mi * 16 * ROWB + ks * 32);
            }
#pragma unroll
            for (int g = 0; g < 2; g++) {
                LDSM_X4(Bf[0][2*g][0], Bf[0][2*g][1], Bf[0][2*g+1][0], Bf[0][2*g+1][1],
                        b_base0 + (uint32_t)g * 16 * ROWB + ks * 32);
                LDSM_X4(Bf[1][2*g][0], Bf[1][2*g][1], Bf[1][2*g+1][0], Bf[1][2*g+1][1],
                        b_base1 + (uint32_t)g * 16 * ROWB + ks * 32);
            }
#pragma unroll
            for (int mi = 0; mi < 4; mi++)
#pragma unroll
                for (int ni = 0; ni < 4; ni++) {
                    MMA16816(acc[mi][ni][0], acc[mi][ni][1], acc[mi][ni][2], acc[mi][ni][3],
                             Af[0][mi][0], Af[0][mi][1], Af[0][mi][2], Af[0][mi][3],
                             Bf[0][ni][0], Bf[0][ni][1]);
                    MMA16816(acc[mi][ni][0], acc[mi][ni][1], acc[mi][ni][2], acc[mi][ni][3],
                             Af[0][mi][0], Af[0][mi][1], Af[0][mi][2], Af[0][mi][3],
                             Bf[1][ni][0], Bf[1][ni][1]);
                    MMA16816(acc[mi][ni][0], acc[mi][ni][1], acc[mi][ni][2], acc[mi][ni][3],
                             Af[1][mi][0], Af[1][mi][1], Af[1][mi][2], Af[1][mi][3],
                             Bf[0][ni][0], Bf[0][ni][1]);
                }
        }
        __syncthreads();
    }

#pragma unroll
    for (int mi = 0; mi < 4; mi++) {
        const int r0 = block_row + m_off + mi * 16 + (lane >> 2);
        const int r1 = r0 + 8;
#pragma unroll
        for (int ni = 0; ni < 4; ni++) {
            const int col = block_col + n_off + ni * 8 + (lane & 3) * 2;
            const float c0 = __ldg(cvec + col);
            const float c1 = __ldg(cvec + col + 1);
            float vals[2][2] = {{acc[mi][ni][0] + c0, acc[mi][ni][1] + c1},
                                {acc[mi][ni][2] + c0, acc[mi][ni][3] + c1}};
            const int rows[2] = {r0, r1};
#pragma unroll
            for (int h = 0; h < 2; h++) {
                const size_t off = (size_t)rows[h] * NHID + col;
                *(float2*)(g_pre + off) = make_float2(vals[h][0], vals[h][1]);
                __nv_bfloat162 mm, aa2, aa3;
#pragma unroll
                for (int e = 0; e < 2; e++) {
                    float px = vals[h][e];
                    __nv_bfloat16 m_ = __float2bfloat16(px > PTHRESH ? 1.0f : 0.0f);
                    __nv_bfloat16 a2_ = __float2bfloat16(px > PTHRESH ? __expf(-px) : 0.0f);
                    __nv_bfloat16 a3_ = __float2bfloat16(px < -PTHRESH ? __expf(px) : 0.0f);
                    if (e == 0) { mm.x = m_; aa2.x = a2_; aa3.x = a3_; }
                    else        { mm.y = m_; aa2.y = a2_; aa3.y = a3_; }
                }
                *(__nv_bfloat162*)(g_m1 + off) = mm;
                *(__nv_bfloat162*)(g_a2 + off) = aa2;
                *(__nv_bfloat162*)(g_a3 + off) = aa3;
            }
        }
    }
}

// ---------------------------------------------------------------------------
// K1b: mask-GEMM, 5 products:
//  G += M1·(uh+um+ul) + A2·e^{-u} + A3·e^{+u}   (split-K into 4 parts)
// ---------------------------------------------------------------------------
#define MG_TA   (128 * ROWB)             // 18432
#define MG_TB   (64 * ROWB)              // 9216
#define MG_BUF  (3 * MG_TA + 5 * MG_TB)  // 101376
#define MG_SMEM (2 * MG_BUF)             // 202752

__global__ __launch_bounds__(256, 1) void maskgemm_kernel() {
    extern __shared__ char smem[];
    const int tid  = threadIdx.x;
    const int wid  = tid >> 5;
    const int lane = tid & 31;
    const int block_row = blockIdx.y * 128;
    const int k_base    = blockIdx.x * 256;

    const __nv_bfloat16* asrc[3] = {g_m1, g_a2, g_a3};
    const __nv_bfloat16* bsrc[5] = {g_uh, g_um, g_ul, g_emu, g_epu};

    auto load_chunk = [&](int k0, int stage) {
        char* bufp = smem + stage * MG_BUF;
#pragma unroll
        for (int t = 0; t < 3; t++) {
#pragma unroll
            for (int i = 0; i < 4; i++) {
                int idx = i * 256 + tid;
                int r = idx >> 3, c = idx & 7;
                CP_ASYNC(smem_u32(bufp + t * MG_TA + r * ROWB + c * 16),
                         asrc[t] + (size_t)(block_row + r) * NHID + k0 + c * 8);
            }
        }
#pragma unroll
        for (int t = 0; t < 5; t++) {
#pragma unroll
            for (int i = 0; i < 2; i++) {
                int idx = i * 256 + tid;
                int r = idx >> 3, c = idx & 7;
                CP_ASYNC(smem_u32(bufp + 3 * MG_TA + t * MG_TB + r * ROWB + c * 16),
                         bsrc[t] + (size_t)r * NHID + k0 + c * 8);
            }
        }
    };

    const int m_off = (wid & 3) * 32;
    const int n_off = (wid >> 2) * 32;

    const uint32_t a_lane = (uint32_t)(m_off + (lane & 15)) * ROWB + (lane >> 4) * 16;
    const uint32_t b_lane = (uint32_t)(n_off + ((lane >> 4) & 1) * 8 + (lane & 7)) * ROWB
                          + ((lane >> 3) & 1) * 16;

    float acc[2][4][4];
#pragma unroll
    for (int mi = 0; mi < 2; mi++)
#pragma unroll
        for (int ni = 0; ni < 4; ni++)
#pragma unroll
            for (int q = 0; q < 4; q++) acc[mi][ni][q] = 0.0f;

    load_chunk(k_base, 0); CP_COMMIT();

    for (int ch = 0; ch < 4; ch++) {
        if (ch + 1 < 4) { load_chunk(k_base + (ch + 1) * KC, (ch + 1) & 1); CP_COMMIT(); CP_WAIT(1); }
        else            { CP_WAIT(0); }
        __syncthreads();

        const char* bufp = smem + (ch & 1) * MG_BUF;
        const uint32_t a_base = smem_u32(bufp) + a_lane;
        const uint32_t b_base = smem_u32(bufp + 3 * MG_TA) + b_lane;

#pragma unroll
        for (int ks = 0; ks < KC / 16; ks++) {
            uint32_t Af[3][2][4];
            uint32_t Bf[5][4][2];
#pragma unroll
            for (int t = 0; t < 3; t++)
#pragma unroll
                for (int mi = 0; mi < 2; mi++)
                    LDSM_X4(Af[t][mi][0], Af[t][mi][1], Af[t][mi][2], Af[t][mi][3],
                            a_base + t * MG_TA + (uint32_t)mi * 16 * ROWB + ks * 32);
#pragma unroll
            for (int t = 0; t < 5; t++)
#pragma unroll
                for (int g = 0; g < 2; g++)
                    LDSM_X4(Bf[t][2*g][0], Bf[t][2*g][1], Bf[t][2*g+1][0], Bf[t][2*g+1][1],
                            b_base + t * MG_TB + (uint32_t)g * 16 * ROWB + ks * 32);
#pragma unroll
            for (int mi = 0; mi < 2; mi++)
#pragma unroll
                for (int ni = 0; ni < 4; ni++) {
                    MMA16816(acc[mi][ni][0], acc[mi][ni][1], acc[mi][ni][2], acc[mi][ni][3],
                             Af[0][mi][0], Af[0][mi][1], Af[0][mi][2], Af[0][mi][3],
                             Bf[0][ni][0], Bf[0][ni][1]);
                    MMA16816(acc[mi][ni][0], acc[mi][ni][1], acc[mi][ni][2], acc[mi][ni][3],
                             Af[0][mi][0], Af[0][mi][1], Af[0][mi][2], Af[0][mi][3],
                             Bf[1][ni][0], Bf[1][ni][1]);
                    MMA16816(acc[mi][ni][0], acc[mi][ni][1], acc[mi][ni][2], acc[mi][ni][3],
                             Af[0][mi][0], Af[0][mi][1], Af[0][mi][2], Af[0][mi][3],
                             Bf[2][ni][0], Bf[2][ni][1]);
                    MMA16816(acc[mi][ni][0], acc[mi][ni][1], acc[mi][ni][2], acc[mi][ni][3],
                             Af[1][mi][0], Af[1][mi][1], Af[1][mi][2], Af[1][mi][3],
                             Bf[3][ni][0], Bf[3][ni][1]);
                    MMA16816(acc[mi][ni][0], acc[mi][ni][1], acc[mi][ni][2], acc[mi][ni][3],
                             Af[2][mi][0], Af[2][mi][1], Af[2][mi][2], Af[2][mi][3],
                             Bf[4][ni][0], Bf[4][ni][1]);
                }
        }
        __syncthreads();
    }

    float* gout = g_G + (size_t)blockIdx.x * B_DIM * NCLASS;
#pragma unroll
    for (int mi = 0; mi < 2; mi++) {
        const int r0 = block_row + m_off + mi * 16 + (lane >> 2);
        const int r1 = r0 + 8;
#pragma unroll
        for (int ni = 0; ni < 4; ni++) {
            const int col = n_off + ni * 8 + (lane & 3) * 2;
            *(float2*)(gout + (size_t)r0 * NCLASS + col) =
                make_float2(acc[mi][ni][0], acc[mi][ni][1]);
            *(float2*)(gout + (size_t)r1 * NCLASS + col) =
                make_float2(acc[mi][ni][2], acc[mi][ni][3]);
        }
    }
}

// ---------------------------------------------------------------------------
// K2: slow-only fenergy partials (|p| <= 14 now), split-j across CTAs.
// ---------------------------------------------------------------------------
#define TJ 128
#define UPAD 133

__global__ __launch_bounds__(256) void fenergy_part_kernel(const float* __restrict__ U) {
    __shared__ float  Us[64 * UPAD];
    __shared__ float  ps[8][TJ];
    __shared__ float2 slist[8][TJ];

    const int tid  = threadIdx.x;
    const int wid  = tid >> 5;
    const int lane = tid & 31;
    const int b0   = blockIdx.y * 8;
    const int jq0  = blockIdx.x * 256;
    const int y0   = lane;
    const int y1   = lane + 32;

    const float* urow0 = &Us[y0 * UPAD];
    const float* urow1 = &Us[y1 * UPAD];

    const float LOG2E = 1.4426950408889634f;
    const float LN2   = 0.6931471805599453f;

    float acc0 = 0.0f, acc1 = 0.0f;

#pragma unroll
    for (int jt = 0; jt < 2; jt++) {
        const int j0 = jq0 + jt * TJ;
#pragma unroll
        for (int i = 0; i < 8; i++) {
            int e  = i * 256 + tid;
            int yy = e >> 5;
            int jqq = (e & 31) * 4;
            float4 u4 = *(const float4*)(U + (size_t)yy * NHID + j0 + jqq);
            float* dst = &Us[yy * UPAD + jqq];
            dst[0] = u4.x; dst[1] = u4.y; dst[2] = u4.z; dst[3] = u4.w;
        }
        {
            int bb = tid >> 5;
            int jqq = (tid & 31) * 4;
            float4 p4 = *(const float4*)(g_pre + (size_t)(b0 + bb) * NHID + j0 + jqq);
            *(float4*)&ps[bb][jqq] = p4;
        }
        __syncthreads();

        int cnt = 0;
#pragma unroll
        for (int s = 0; s < 4; s++) {
            int jj = s * 32 + lane;
            float p = ps[wid][jj];
            bool slow = fabsf(p) <= PTHRESH;
            unsigned mask = __ballot_sync(0xffffffffu, slow);
            int rank = __popc(mask & ((1u << lane) - 1u));
            if (slow) slist[wid][cnt + rank] = make_float2(__int_as_float(jj), p);
            cnt += __popc(mask);
        }

        float a0 = 0.f, a1 = 0.f;
        float c0 = 0.f, c1 = 0.f;
        float P0 = 1.f, P1 = 1.f;
#pragma unroll 2
        for (int i = 0; i < cnt; i++) {
            float2 e = slist[wid][i];
            int jj  = __float_as_int(e.x);
            float p = e.y;
            float x0 = p + urow0[jj];
            float x1 = p + urow1[jj];
            a0 += fmaxf(x0, 0.f);
            a1 += fmaxf(x1, 0.f);
            P0 = fmaf(P0, exp2f(-fabsf(x0) * LOG2E), P0);
            P1 = fmaf(P1, exp2f(-fabsf(x1) * LOG2E), P1);
            if ((i & 31) == 31) {
                c0 += __log2f(P0); P0 = 1.f;
                c1 += __log2f(P1); P1 = 1.f;
            }
        }
        c0 += __log2f(P0);
        c1 += __log2f(P1);

        acc0 += a0 + LN2 * c0;
        acc1 += a1 + LN2 * c1;
        __syncthreads();
    }

    const int b = b0 + wid;
    float* fp = g_Fp + (size_t)blockIdx.x * B_DIM * NCLASS + (size_t)b * NCLASS;
    fp[y0] = acc0;
    fp[y1] = acc1;
}

// ---------------------------------------------------------------------------
// K3: combine partials + softmax + argmax + one_hot. Warp = batch row.
// ---------------------------------------------------------------------------
__global__ __launch_bounds__(256) void combine_kernel(const float* __restrict__ dvec,
                                                      float* __restrict__ out) {
    const int wid  = threadIdx.x >> 5;
    const int lane = threadIdx.x & 31;
    const int b    = blockIdx.x * 8 + wid;
    const int y0   = lane;
    const int y1   = lane + 32;

    float f0 = __ldg(dvec + y0);
    float f1 = __ldg(dvec + y1);
#pragma unroll
    for (int q = 0; q < 4; q++) {
        const size_t off = (size_t)q * B_DIM * NCLASS + (size_t)b * NCLASS;
        f0 += g_G[off + y0] + g_Fp[off + y0];
        f1 += g_G[off + y1] + g_Fp[off + y1];
    }

    float m = fmaxf(f0, f1);
#pragma unroll
    for (int o = 16; o > 0; o >>= 1) m = fmaxf(m, __shfl_xor_sync(0xffffffffu, m, o));
    float e0 = __expf(f0 - m);
    float e1 = __expf(f1 - m);
    float s = e0 + e1;
#pragma unroll
    for (int o = 16; o > 0; o >>= 1) s += __shfl_xor_sync(0xffffffffu, s, o);
    float inv = 1.0f / s;
    float p0 = e0 * inv;
    float p1 = e1 * inv;

    float pm = p0; int im = y0;
    if (p1 > pm) { pm = p1; im = y1; }
#pragma unroll
    for (int o = 16; o > 0; o >>= 1) {
        float po = __shfl_xor_sync(0xffffffffu, pm, o);
        int   io = __shfl_xor_sync(0xffffffffu, im, o);
        if (po > pm || (po == pm && io < im)) { pm = po; im = io; }
    }

    out[(size_t)b * NCLASS + y0] = p0;
    out[(size_t)b * NCLASS + y1] = p1;
    float* oh = out + (size_t)B_DIM * NCLASS;
    oh[(size_t)b * NCLASS + y0] = (y0 == im) ? 1.0f : 0.0f;
    oh[(size_t)b * NCLASS + y1] = (y1 == im) ? 1.0f : 0.0f;
}

// ---------------------------------------------------------------------------
extern "C" void kernel_launch(void* const* d_in, const int* in_sizes, int n_in,
                              void* d_out, int out_size) {
    const float* v = (const float*)d_in[0];
    const float* W = (const float*)d_in[1];
    const float* c = (const float*)d_in[2];
    const float* d = (const float*)d_in[3];
    const float* U = (const float*)d_in[4];
    float* out = (float*)d_out;

    cudaFuncSetAttribute(gemm_mma_kernel,
                         cudaFuncAttributeMaxDynamicSharedMemorySize, GEMM_SMEM);
    cudaFuncSetAttribute(maskgemm_kernel,
                         cudaFuncAttributeMaxDynamicSharedMemorySize, MG_SMEM);

    split_kernel<<<3088, 256>>>(v, W, U);
    gemm_mma_kernel<<<dim3(NHID / 128, B_DIM / 128), 256, GEMM_SMEM>>>(c);
    maskgemm_kernel<<<dim3(4, B_DIM / 128), 256, MG_SMEM>>>();
    fenergy_part_kernel<<<dim3(4, B_DIM / 8), 256>>>(U);
    combine_kernel<<<B_DIM / 8, 256>>>(d, out);
}

// round 15
// speedup vs baseline: 1.0125x; 1.0125x over previous
#include <cuda_runtime.h>
#include <cuda_bf16.h>
#include <cstdint>

#define B_DIM  2048
#define NVIS   2048
#define NHID   1024
#define NCLASS 64

// ---------------------------------------------------------------------------
// Static device scratch
// ---------------------------------------------------------------------------
__device__ float g_pre[B_DIM * NHID];                 // 8 MB
__device__ __nv_bfloat16 g_vh[B_DIM * NVIS];          // 8 MB
__device__ __nv_bfloat16 g_vm[B_DIM * NVIS];          // 8 MB
__device__ __nv_bfloat16 g_wh[NHID * NVIS];           // 4 MB (W^T limbs, [n][k])
__device__ __nv_bfloat16 g_wm[NHID * NVIS];           // 4 MB
__device__ __nv_bfloat16 g_mask[B_DIM * NHID];        // 4 MB  M[b][j] = 1[p>21]
__device__ __nv_bfloat16 g_uh[NCLASS * NHID];         // U limbs [y][j]
__device__ __nv_bfloat16 g_um[NCLASS * NHID];
__device__ __nv_bfloat16 g_ul[NCLASS * NHID];
__device__ float g_G[4 * B_DIM * NCLASS];             // 2 MB  split-K mask-GEMM parts
__device__ float g_Fp[2 * B_DIM * NCLASS];            // 1 MB  split-j fenergy partials

__device__ __forceinline__ uint32_t smem_u32(const void* p) {
    uint32_t a;
    asm("{ .reg .u64 t; cvta.to.shared.u64 t, %1; cvt.u32.u64 %0, t; }" : "=r"(a) : "l"(p));
    return a;
}

// ---------------------------------------------------------------------------
// K0: fused split kernel: v limbs, W^T limbs, U 3-limb copies
// ---------------------------------------------------------------------------
__global__ __launch_bounds__(256) void split_kernel(const float* __restrict__ v,
                                                    const float* __restrict__ W,
                                                    const float* __restrict__ U) {
    if (blockIdx.x < 1024) {
        const int base = blockIdx.x * 1024 + threadIdx.x;   // float4 index
        float4 x[4];
#pragma unroll
        for (int r = 0; r < 4; r++)
            x[r] = *(const float4*)(v + (size_t)(base + r * 256) * 4);
#pragma unroll
        for (int r = 0; r < 4; r++) {
            float xs[4] = {x[r].x, x[r].y, x[r].z, x[r].w};
            __nv_bfloat16 hb[4], mb[4];
#pragma unroll
            for (int i = 0; i < 4; i++) {
                hb[i] = __float2bfloat16(xs[i]);
                mb[i] = __float2bfloat16(xs[i] - __bfloat162float(hb[i]));
            }
            size_t o = (size_t)(base + r * 256) * 4;
            *(uint2*)(g_vh + o) = *(uint2*)hb;
            *(uint2*)(g_vm + o) = *(uint2*)mb;
        }
    } else if (blockIdx.x < 3072) {
        __shared__ float s[32][33];
        int bid = blockIdx.x - 1024;
        int nb = (bid & 31) * 32;
        int kb = (bid >> 5) * 32;
        int tx = threadIdx.x & 31;
        int ty = threadIdx.x >> 5;
        float w[4];
#pragma unroll
        for (int i = 0; i < 4; i++)
            w[i] = W[(size_t)(kb + ty + i * 8) * NHID + nb + tx];
#pragma unroll
        for (int i = 0; i < 4; i++)
            s[ty + i * 8][tx] = w[i];
        __syncthreads();
#pragma unroll
        for (int i = 0; i < 4; i++) {
            int n = ty + i * 8;
            float x = s[tx][n];
            __nv_bfloat16 h = __float2bfloat16(x);
            __nv_bfloat16 m = __float2bfloat16(x - __bfloat162float(h));
            size_t o = (size_t)(nb + n) * NVIS + kb + tx;
            g_wh[o] = h; g_wm[o] = m;
        }
    } else {
        // U 3-limb split: 16 blocks x 256 threads x 4 float4 = 65536 elems
        const int base = (blockIdx.x - 3072) * 1024 + threadIdx.x;
#pragma unroll
        for (int r = 0; r < 4; r++) {
            int idx = base + r * 256;
            float4 x4 = *(const float4*)(U + (size_t)idx * 4);
            float xs[4] = {x4.x, x4.y, x4.z, x4.w};
            __nv_bfloat16 hb[4], mb[4], lb[4];
#pragma unroll
            for (int i = 0; i < 4; i++) {
                hb[i] = __float2bfloat16(xs[i]);
                float r1 = xs[i] - __bfloat162float(hb[i]);
                mb[i] = __float2bfloat16(r1);
                lb[i] = __float2bfloat16(r1 - __bfloat162float(mb[i]));
            }
            size_t o = (size_t)idx * 4;
            *(uint2*)(g_uh + o) = *(uint2*)hb;
            *(uint2*)(g_um + o) = *(uint2*)mb;
            *(uint2*)(g_ul + o) = *(uint2*)lb;
        }
    }
}

// ---------------------------------------------------------------------------
// Shared GEMM macros
// ---------------------------------------------------------------------------
#define CP_ASYNC(dst, src) \
    asm volatile("cp.async.cg.shared.global [%0], [%1], 16;" :: "r"(dst), "l"(src))
#define CP_COMMIT() asm volatile("cp.async.commit_group;" ::: "memory")
#define CP_WAIT(n)  asm volatile("cp.async.wait_group %0;" :: "n"(n) : "memory")

#define LDSM_X4(r0, r1, r2, r3, a) \
    asm volatile("ldmatrix.sync.aligned.m8n8.x4.shared.b16 {%0,%1,%2,%3}, [%4];" \
        : "=r"(r0), "=r"(r1), "=r"(r2), "=r"(r3) : "r"(a))

#define MMA16816(c0, c1, c2, c3, a0, a1, a2, a3, b0, b1) \
    asm volatile("mma.sync.aligned.m16n8k16.row.col.f32.bf16.bf16.f32 " \
        "{%0,%1,%2,%3}, {%4,%5,%6,%7}, {%8,%9}, {%0,%1,%2,%3};" \
        : "+f"(c0), "+f"(c1), "+f"(c2), "+f"(c3) \
        : "r"(a0), "r"(a1), "r"(a2), "r"(a3), "r"(b0), "r"(b1))

// ---------------------------------------------------------------------------
// K1: pre = v @ W + c  (proven config) + mask write in epilogue
// ---------------------------------------------------------------------------
#define KC        64
#define ROWB      144
#define TILEB     (128 * ROWB)
#define BUFB      (4 * TILEB)
#define STAGES    3
#define GEMM_SMEM (STAGES * BUFB)        // 221184

__global__ __launch_bounds__(256, 1) void gemm_mma_kernel(const float* __restrict__ cvec) {
    extern __shared__ char smem[];
    const int tid  = threadIdx.x;
    const int wid  = tid >> 5;
    const int lane = tid & 31;
    const int block_row = blockIdx.y * 128;
    const int block_col = blockIdx.x * 128;

    const __nv_bfloat16* srcs[4] = {g_vh, g_vm, g_wh, g_wm};

    auto load_chunk = [&](int k0, int stage) {
        char* bufp = smem + stage * BUFB;
#pragma unroll
        for (int t = 0; t < 4; t++) {
            const int row0 = (t < 2) ? block_row : block_col;
            const __nv_bfloat16* src = srcs[t];
#pragma unroll
            for (int i = 0; i < 4; i++) {
                int idx = i * 256 + tid;
                int r = idx >> 3;
                int c = idx & 7;
                const void* g = src + (size_t)(row0 + r) * NVIS + k0 + c * 8;
                uint32_t d = smem_u32(bufp + t * TILEB + r * ROWB + c * 16);
                CP_ASYNC(d, g);
            }
        }
    };

    const int m_off = (wid >> 2) * 64;
    const int n_off = (wid & 3) * 32;

    const uint32_t a_lane = (uint32_t)(m_off + (lane & 15)) * ROWB + (lane >> 4) * 16;
    const uint32_t b_lane = (uint32_t)(n_off + ((lane >> 4) & 1) * 8 + (lane & 7)) * ROWB
                          + ((lane >> 3) & 1) * 16;

    float acc[4][4][4];
#pragma unroll
    for (int mi = 0; mi < 4; mi++)
#pragma unroll
        for (int ni = 0; ni < 4; ni++)
#pragma unroll
            for (int q = 0; q < 4; q++) acc[mi][ni][q] = 0.0f;

    const int NCHUNK = NVIS / KC;

    load_chunk(0, 0); CP_COMMIT();
    load_chunk(KC, 1); CP_COMMIT();

    for (int ch = 0; ch < NCHUNK; ch++) {
        if (ch + 2 < NCHUNK) { load_chunk((ch + 2) * KC, (ch + 2) % STAGES); CP_COMMIT(); }
        if (ch + 2 < NCHUNK)      { CP_WAIT(2); }
        else if (ch + 1 < NCHUNK) { CP_WAIT(1); }
        else                      { CP_WAIT(0); }
        __syncthreads();

        const char* bufp = smem + (ch % STAGES) * BUFB;
        const uint32_t a_base0 = smem_u32(bufp) + a_lane;
        const uint32_t a_base1 = a_base0 + TILEB;
        const uint32_t b_base0 = smem_u32(bufp + 2 * TILEB) + b_lane;
        const uint32_t b_base1 = b_base0 + TILEB;

#pragma unroll
        for (int ks = 0; ks < KC / 16; ks++) {
            uint32_t Af[2][4][4];
            uint32_t Bf[2][4][2];
#pragma unroll
            for (int mi = 0; mi < 4; mi++) {
                LDSM_X4(Af[0][mi][0], Af[0][mi][1], Af[0][mi][2], Af[0][mi][3],
                        a_base0 + (uint32_t)mi * 16 * ROWB + ks * 32);
                LDSM_X4(Af[1][mi][0], Af[1][mi][1], Af[1][mi][2], Af[1][mi][3],
                        a_base1 + (uint32_t)mi * 16 * ROWB + ks * 32);
            }
#pragma unroll
            for (int g = 0; g < 2; g++) {
                LDSM_X4(Bf[0][2*g][0], Bf[0][2*g][1], Bf[0][2*g+1][0], Bf[0][2*g+1][1],
                        b_base0 + (uint32_t)g * 16 * ROWB + ks * 32);
                LDSM_X4(Bf[1][2*g][0], Bf[1][2*g][1], Bf[1][2*g+1][0], Bf[1][2*g+1][1],
                        b_base1 + (uint32_t)g * 16 * ROWB + ks * 32);
            }
#pragma unroll
            for (int mi = 0; mi < 4; mi++)
#pragma unroll
                for (int ni = 0; ni < 4; ni++) {
                    MMA16816(acc[mi][ni][0], acc[mi][ni][1], acc[mi][ni][2], acc[mi][ni][3],
                             Af[0][mi][0], Af[0][mi][1], Af[0][mi][2], Af[0][mi][3],
                             Bf[0][ni][0], Bf[0][ni][1]);
                    MMA16816(acc[mi][ni][0], acc[mi][ni][1], acc[mi][ni][2], acc[mi][ni][3],
                             Af[0][mi][0], Af[0][mi][1], Af[0][mi][2], Af[0][mi][3],
                             Bf[1][ni][0], Bf[1][ni][1]);
                    MMA16816(acc[mi][ni][0], acc[mi][ni][1], acc[mi][ni][2], acc[mi][ni][3],
                             Af[1][mi][0], Af[1][mi][1], Af[1][mi][2], Af[1][mi][3],
                             Bf[0][ni][0], Bf[0][ni][1]);
                }
        }
        __syncthreads();
    }

#pragma unroll
    for (int mi = 0; mi < 4; mi++) {
        const int r0 = block_row + m_off + mi * 16 + (lane >> 2);
        const int r1 = r0 + 8;
#pragma unroll
        for (int ni = 0; ni < 4; ni++) {
            const int col = block_col + n_off + ni * 8 + (lane & 3) * 2;
            const float c0 = __ldg(cvec + col);
            const float c1 = __ldg(cvec + col + 1);
            float2 o0 = {acc[mi][ni][0] + c0, acc[mi][ni][1] + c1};
            float2 o1 = {acc[mi][ni][2] + c0, acc[mi][ni][3] + c1};
            *(float2*)(g_pre + (size_t)r0 * NHID + col) = o0;
            *(float2*)(g_pre + (size_t)r1 * NHID + col) = o1;
            __nv_bfloat162 m0, m1;
            m0.x = __float2bfloat16(o0.x > 21.0f ? 1.0f : 0.0f);
            m0.y = __float2bfloat16(o0.y > 21.0f ? 1.0f : 0.0f);
            m1.x = __float2bfloat16(o1.x > 21.0f ? 1.0f : 0.0f);
            m1.y = __float2bfloat16(o1.y > 21.0f ? 1.0f : 0.0f);
            *(__nv_bfloat162*)(g_mask + (size_t)r0 * NHID + col) = m0;
            *(__nv_bfloat162*)(g_mask + (size_t)r1 * NHID + col) = m1;
        }
    }
}

// ---------------------------------------------------------------------------
// K1b: mask-GEMM  G_part[kq][b][y] = sum_{j in kq} M[b][j] * U[y][j]  (3-limb)
// ---------------------------------------------------------------------------
#define MG_TA   (128 * ROWB)
#define MG_TU   (64 * ROWB)
#define MG_BUF  (MG_TA + 3 * MG_TU)
#define MG_SMEM (2 * MG_BUF)

__global__ __launch_bounds__(256, 2) void maskgemm_kernel() {
    extern __shared__ char smem[];
    const int tid  = threadIdx.x;
    const int wid  = tid >> 5;
    const int lane = tid & 31;
    const int block_row = blockIdx.y * 128;
    const int k_base    = blockIdx.x * 256;

    const __nv_bfloat16* usrc[3] = {g_uh, g_um, g_ul};

    auto load_chunk = [&](int k0, int stage) {
        char* bufp = smem + stage * MG_BUF;
#pragma unroll
        for (int i = 0; i < 4; i++) {
            int idx = i * 256 + tid;
            int r = idx >> 3, c = idx & 7;
            CP_ASYNC(smem_u32(bufp + r * ROWB + c * 16),
                     g_mask + (size_t)(block_row + r) * NHID + k0 + c * 8);
        }
#pragma unroll
        for (int t = 0; t < 3; t++) {
#pragma unroll
            for (int i = 0; i < 2; i++) {
                int idx = i * 256 + tid;
                int r = idx >> 3, c = idx & 7;
                CP_ASYNC(smem_u32(bufp + MG_TA + t * MG_TU + r * ROWB + c * 16),
                         usrc[t] + (size_t)r * NHID + k0 + c * 8);
            }
        }
    };

    const int m_off = (wid & 3) * 32;
    const int n_off = (wid >> 2) * 32;

    const uint32_t a_lane = (uint32_t)(m_off + (lane & 15)) * ROWB + (lane >> 4) * 16;
    const uint32_t b_lane = (uint32_t)(n_off + ((lane >> 4) & 1) * 8 + (lane & 7)) * ROWB
                          + ((lane >> 3) & 1) * 16;

    float acc[2][4][4];
#pragma unroll
    for (int mi = 0; mi < 2; mi++)
#pragma unroll
        for (int ni = 0; ni < 4; ni++)
#pragma unroll
            for (int q = 0; q < 4; q++) acc[mi][ni][q] = 0.0f;

    load_chunk(k_base, 0); CP_COMMIT();

    for (int ch = 0; ch < 4; ch++) {
        if (ch + 1 < 4) { load_chunk(k_base + (ch + 1) * KC, (ch + 1) & 1); CP_COMMIT(); CP_WAIT(1); }
        else            { CP_WAIT(0); }
        __syncthreads();

        const char* bufp = smem + (ch & 1) * MG_BUF;
        const uint32_t a_base = smem_u32(bufp) + a_lane;
        const uint32_t b_base = smem_u32(bufp + MG_TA) + b_lane;

#pragma unroll
        for (int ks = 0; ks < KC / 16; ks++) {
            uint32_t Af[2][4];
            uint32_t Bf[3][4][2];
#pragma unroll
            for (int mi = 0; mi < 2; mi++)
                LDSM_X4(Af[mi][0], Af[mi][1], Af[mi][2], Af[mi][3],
                        a_base + (uint32_t)mi * 16 * ROWB + ks * 32);
#pragma unroll
            for (int t = 0; t < 3; t++)
#pragma unroll
                for (int g = 0; g < 2; g++)
                    LDSM_X4(Bf[t][2*g][0], Bf[t][2*g][1], Bf[t][2*g+1][0], Bf[t][2*g+1][1],
                            b_base + t * MG_TU + (uint32_t)g * 16 * ROWB + ks * 32);
#pragma unroll
            for (int mi = 0; mi < 2; mi++)
#pragma unroll
                for (int ni = 0; ni < 4; ni++)
#pragma unroll
                    for (int t = 0; t < 3; t++)
                        MMA16816(acc[mi][ni][0], acc[mi][ni][1], acc[mi][ni][2], acc[mi][ni][3],
                                 Af[mi][0], Af[mi][1], Af[mi][2], Af[mi][3],
                                 Bf[t][ni][0], Bf[t][ni][1]);
        }
        __syncthreads();
    }

    float* gout = g_G + (size_t)blockIdx.x * B_DIM * NCLASS;
#pragma unroll
    for (int mi = 0; mi < 2; mi++) {
        const int r0 = block_row + m_off + mi * 16 + (lane >> 2);
        const int r1 = r0 + 8;
#pragma unroll
        for (int ni = 0; ni < 4; ni++) {
            const int col = n_off + ni * 8 + (lane & 3) * 2;
            *(float2*)(gout + (size_t)r0 * NCLASS + col) =
                make_float2(acc[mi][ni][0], acc[mi][ni][1]);
            *(float2*)(gout + (size_t)r1 * NCLASS + col) =
                make_float2(acc[mi][ni][2], acc[mi][ni][3]);
        }
    }
}

// ---------------------------------------------------------------------------
// K2: slow-only fenergy partials, split-j across CTAs.
// Grid (2 j-halves, 256 row-blocks) = 512 CTAs -> SINGLE fully-resident wave
// (512 < 592 resident slots at 4 CTAs/SM). 8 rows/CTA (warp = row); each CTA
// covers 512 j's (4 tiles of 128).
// ---------------------------------------------------------------------------
#define TJ 128
#define UPAD 133

__global__ __launch_bounds__(256) void fenergy_part_kernel(const float* __restrict__ U) {
    __shared__ float  Us[64 * UPAD];
    __shared__ float  ps[8][TJ];
    __shared__ float2 slist[8][TJ];

    const int tid  = threadIdx.x;
    const int wid  = tid >> 5;
    const int lane = tid & 31;
    const int b0   = blockIdx.y * 8;
    const int jq0  = blockIdx.x * 512;       // this CTA's j-half
    const int y0   = lane;
    const int y1   = lane + 32;

    const float* urow0 = &Us[y0 * UPAD];
    const float* urow1 = &Us[y1 * UPAD];

    const float LOG2E = 1.4426950408889634f;
    const float LN2   = 0.6931471805599453f;

    float acc0 = 0.0f, acc1 = 0.0f;

#pragma unroll 1
    for (int jt = 0; jt < 4; jt++) {
        const int j0 = jq0 + jt * TJ;
        // ---- fill U tile (64 x 128) ----
#pragma unroll
        for (int i = 0; i < 8; i++) {
            int e  = i * 256 + tid;
            int yy = e >> 5;
            int jqq = (e & 31) * 4;
            float4 u4 = *(const float4*)(U + (size_t)yy * NHID + j0 + jqq);
            float* dst = &Us[yy * UPAD + jqq];
            dst[0] = u4.x; dst[1] = u4.y; dst[2] = u4.z; dst[3] = u4.w;
        }
        // ---- fill p tile (8 x 128) ----
        {
            int bb = tid >> 5;
            int jqq = (tid & 31) * 4;
            float4 p4 = *(const float4*)(g_pre + (size_t)(b0 + bb) * NHID + j0 + jqq);
            *(float4*)&ps[bb][jqq] = p4;
        }
        __syncthreads();

        // slow list: |p| <= 21
        int cnt = 0;
#pragma unroll
        for (int s = 0; s < 4; s++) {
            int jj = s * 32 + lane;
            float p = ps[wid][jj];
            bool slow = fabsf(p) <= 21.0f;
            unsigned mask = __ballot_sync(0xffffffffu, slow);
            int rank = __popc(mask & ((1u << lane) - 1u));
            if (slow) slist[wid][cnt + rank] = make_float2(__int_as_float(jj), p);
            cnt += __popc(mask);
        }

        // slow-only full softplus (log-product trick)
        float a0 = 0.f, a1 = 0.f;
        float c0 = 0.f, c1 = 0.f;
        float P0 = 1.f, P1 = 1.f;
        for (int i = 0; i < cnt; i++) {
            float2 e = slist[wid][i];
            int jj  = __float_as_int(e.x);
            float p = e.y;
            float x0 = p + urow0[jj];
            float x1 = p + urow1[jj];
            a0 += fmaxf(x0, 0.f);
            a1 += fmaxf(x1, 0.f);
            P0 = fmaf(P0, exp2f(-fabsf(x0) * LOG2E), P0);
            P1 = fmaf(P1, exp2f(-fabsf(x1) * LOG2E), P1);
            if ((i & 31) == 31) {
                c0 += __log2f(P0); P0 = 1.f;
                c1 += __log2f(P1); P1 = 1.f;
            }
        }
        c0 += __log2f(P0);
        c1 += __log2f(P1);

        acc0 += a0 + LN2 * c0;
        acc1 += a1 + LN2 * c1;
        __syncthreads();
    }

    const int b = b0 + wid;
    float* fp = g_Fp + (size_t)blockIdx.x * B_DIM * NCLASS + (size_t)b * NCLASS;
    fp[y0] = acc0;
    fp[y1] = acc1;
}

// ---------------------------------------------------------------------------
// K3: combine partials + softmax + argmax + one_hot. Warp = batch row.
// ---------------------------------------------------------------------------
__global__ __launch_bounds__(256) void combine_kernel(const float* __restrict__ dvec,
                                                      float* __restrict__ out) {
    const int wid  = threadIdx.x >> 5;
    const int lane = threadIdx.x & 31;
    const int b    = blockIdx.x * 8 + wid;
    const int y0   = lane;
    const int y1   = lane + 32;

    float f0 = __ldg(dvec + y0);
    float f1 = __ldg(dvec + y1);
#pragma unroll
    for (int q = 0; q < 4; q++) {
        const size_t off = (size_t)q * B_DIM * NCLASS + (size_t)b * NCLASS;
        f0 += g_G[off + y0];
        f1 += g_G[off + y1];
    }
#pragma unroll
    for (int q = 0; q < 2; q++) {
        const size_t off = (size_t)q * B_DIM * NCLASS + (size_t)b * NCLASS;
        f0 += g_Fp[off + y0];
        f1 += g_Fp[off + y1];
    }

    float m = fmaxf(f0, f1);
#pragma unroll
    for (int o = 16; o > 0; o >>= 1) m = fmaxf(m, __shfl_xor_sync(0xffffffffu, m, o));
    float e0 = __expf(f0 - m);
    float e1 = __expf(f1 - m);
    float s = e0 + e1;
#pragma unroll
    for (int o = 16; o > 0; o >>= 1) s += __shfl_xor_sync(0xffffffffu, s, o);
    float inv = 1.0f / s;
    float p0 = e0 * inv;
    float p1 = e1 * inv;

    float pm = p0; int im = y0;
    if (p1 > pm) { pm = p1; im = y1; }
#pragma unroll
    for (int o = 16; o > 0; o >>= 1) {
        float po = __shfl_xor_sync(0xffffffffu, pm, o);
        int   io = __shfl_xor_sync(0xffffffffu, im, o);
        if (po > pm || (po == pm && io < im)) { pm = po; im = io; }
    }

    out[(size_t)b * NCLASS + y0] = p0;
    out[(size_t)b * NCLASS + y1] = p1;
    float* oh = out + (size_t)B_DIM * NCLASS;
    oh[(size_t)b * NCLASS + y0] = (y0 == im) ? 1.0f : 0.0f;
    oh[(size_t)b * NCLASS + y1] = (y1 == im) ? 1.0f : 0.0f;
}

// ---------------------------------------------------------------------------
extern "C" void kernel_launch(void* const* d_in, const int* in_sizes, int n_in,
                              void* d_out, int out_size) {
    const float* v = (const float*)d_in[0];
    const float* W = (const float*)d_in[1];
    const float* c = (const float*)d_in[2];
    const float* d = (const float*)d_in[3];
    const float* U = (const float*)d_in[4];
    float* out = (float*)d_out;

    cudaFuncSetAttribute(gemm_mma_kernel,
                         cudaFuncAttributeMaxDynamicSharedMemorySize, GEMM_SMEM);
    cudaFuncSetAttribute(maskgemm_kernel,
                         cudaFuncAttributeMaxDynamicSharedMemorySize, MG_SMEM);

    split_kernel<<<3088, 256>>>(v, W, U);
    gemm_mma_kernel<<<dim3(NHID / 128, B_DIM / 128), 256, GEMM_SMEM>>>(c);
    maskgemm_kernel<<<dim3(4, B_DIM / 128), 256, MG_SMEM>>>();
    fenergy_part_kernel<<<dim3(2, B_DIM / 8), 256>>>(U);
    combine_kernel<<<B_DIM / 8, 256>>>(d, out);
}

// round 16
// speedup vs baseline: 1.0820x; 1.0687x over previous
#include <cuda_runtime.h>
#include <cuda_bf16.h>
#include <cstdint>

#define B_DIM  2048
#define NVIS   2048
#define NHID   1024
#define NCLASS 64

// ---------------------------------------------------------------------------
// Static device scratch
// ---------------------------------------------------------------------------
__device__ float g_pre[B_DIM * NHID];                 // 8 MB
__device__ __nv_bfloat16 g_vh[B_DIM * NVIS];          // 8 MB
__device__ __nv_bfloat16 g_vm[B_DIM * NVIS];          // 8 MB
__device__ __nv_bfloat16 g_wh[NHID * NVIS];           // 4 MB (W^T limbs, [n][k])
__device__ __nv_bfloat16 g_wm[NHID * NVIS];           // 4 MB
__device__ __nv_bfloat16 g_mask[B_DIM * NHID];        // 4 MB  M[b][j] = 1[p>21]
__device__ __nv_bfloat16 g_uh[NCLASS * NHID];         // U limbs [y][j]
__device__ __nv_bfloat16 g_um[NCLASS * NHID];
__device__ __nv_bfloat16 g_ul[NCLASS * NHID];
__device__ float g_G[4 * B_DIM * NCLASS];             // 2 MB  split-K mask-GEMM parts
__device__ float g_Fp[4 * B_DIM * NCLASS];            // 2 MB  split-j fenergy partials

__device__ __forceinline__ uint32_t smem_u32(const void* p) {
    uint32_t a;
    asm("{ .reg .u64 t; cvta.to.shared.u64 t, %1; cvt.u32.u64 %0, t; }" : "=r"(a) : "l"(p));
    return a;
}

// ---------------------------------------------------------------------------
// K0: fused split kernel: v limbs, W^T limbs, U 3-limb copies
// ---------------------------------------------------------------------------
__global__ __launch_bounds__(256) void split_kernel(const float* __restrict__ v,
                                                    const float* __restrict__ W,
                                                    const float* __restrict__ U) {
    if (blockIdx.x < 1024) {
        const int base = blockIdx.x * 1024 + threadIdx.x;   // float4 index
        float4 x[4];
#pragma unroll
        for (int r = 0; r < 4; r++)
            x[r] = *(const float4*)(v + (size_t)(base + r * 256) * 4);
#pragma unroll
        for (int r = 0; r < 4; r++) {
            float xs[4] = {x[r].x, x[r].y, x[r].z, x[r].w};
            __nv_bfloat16 hb[4], mb[4];
#pragma unroll
            for (int i = 0; i < 4; i++) {
                hb[i] = __float2bfloat16(xs[i]);
                mb[i] = __float2bfloat16(xs[i] - __bfloat162float(hb[i]));
            }
            size_t o = (size_t)(base + r * 256) * 4;
            *(uint2*)(g_vh + o) = *(uint2*)hb;
            *(uint2*)(g_vm + o) = *(uint2*)mb;
        }
    } else if (blockIdx.x < 3072) {
        __shared__ float s[32][33];
        int bid = blockIdx.x - 1024;
        int nb = (bid & 31) * 32;
        int kb = (bid >> 5) * 32;
        int tx = threadIdx.x & 31;
        int ty = threadIdx.x >> 5;
        float w[4];
#pragma unroll
        for (int i = 0; i < 4; i++)
            w[i] = W[(size_t)(kb + ty + i * 8) * NHID + nb + tx];
#pragma unroll
        for (int i = 0; i < 4; i++)
            s[ty + i * 8][tx] = w[i];
        __syncthreads();
#pragma unroll
        for (int i = 0; i < 4; i++) {
            int n = ty + i * 8;
            float x = s[tx][n];
            __nv_bfloat16 h = __float2bfloat16(x);
            __nv_bfloat16 m = __float2bfloat16(x - __bfloat162float(h));
            size_t o = (size_t)(nb + n) * NVIS + kb + tx;
            g_wh[o] = h; g_wm[o] = m;
        }
    } else {
        // U 3-limb split: 16 blocks x 256 threads x 4 float4 = 65536 elems
        const int base = (blockIdx.x - 3072) * 1024 + threadIdx.x;
#pragma unroll
        for (int r = 0; r < 4; r++) {
            int idx = base + r * 256;
            float4 x4 = *(const float4*)(U + (size_t)idx * 4);
            float xs[4] = {x4.x, x4.y, x4.z, x4.w};
            __nv_bfloat16 hb[4], mb[4], lb[4];
#pragma unroll
            for (int i = 0; i < 4; i++) {
                hb[i] = __float2bfloat16(xs[i]);
                float r1 = xs[i] - __bfloat162float(hb[i]);
                mb[i] = __float2bfloat16(r1);
                lb[i] = __float2bfloat16(r1 - __bfloat162float(mb[i]));
            }
            size_t o = (size_t)idx * 4;
            *(uint2*)(g_uh + o) = *(uint2*)hb;
            *(uint2*)(g_um + o) = *(uint2*)mb;
            *(uint2*)(g_ul + o) = *(uint2*)lb;
        }
    }
}

// ---------------------------------------------------------------------------
// Shared GEMM macros
// ---------------------------------------------------------------------------
#define CP_ASYNC(dst, src) \
    asm volatile("cp.async.cg.shared.global [%0], [%1], 16;" :: "r"(dst), "l"(src))
#define CP_COMMIT() asm volatile("cp.async.commit_group;" ::: "memory")
#define CP_WAIT(n)  asm volatile("cp.async.wait_group %0;" :: "n"(n) : "memory")

#define LDSM_X4(r0, r1, r2, r3, a) \
    asm volatile("ldmatrix.sync.aligned.m8n8.x4.shared.b16 {%0,%1,%2,%3}, [%4];" \
        : "=r"(r0), "=r"(r1), "=r"(r2), "=r"(r3) : "r"(a))

#define MMA16816(c0, c1, c2, c3, a0, a1, a2, a3, b0, b1) \
    asm volatile("mma.sync.aligned.m16n8k16.row.col.f32.bf16.bf16.f32 " \
        "{%0,%1,%2,%3}, {%4,%5,%6,%7}, {%8,%9}, {%0,%1,%2,%3};" \
        : "+f"(c0), "+f"(c1), "+f"(c2), "+f"(c3) \
        : "r"(a0), "r"(a1), "r"(a2), "r"(a3), "r"(b0), "r"(b1))

// ---------------------------------------------------------------------------
// K1: pre = v @ W + c  (proven config) + mask write in epilogue
// ---------------------------------------------------------------------------
#define KC        64
#define ROWB      144
#define TILEB     (128 * ROWB)
#define BUFB      (4 * TILEB)
#define STAGES    3
#define GEMM_SMEM (STAGES * BUFB)        // 221184

__global__ __launch_bounds__(256, 1) void gemm_mma_kernel(const float* __restrict__ cvec) {
    extern __shared__ char smem[];
    const int tid  = threadIdx.x;
    const int wid  = tid >> 5;
    const int lane = tid & 31;
    const int block_row = blockIdx.y * 128;
    const int block_col = blockIdx.x * 128;

    const __nv_bfloat16* srcs[4] = {g_vh, g_vm, g_wh, g_wm};

    auto load_chunk = [&](int k0, int stage) {
        char* bufp = smem + stage * BUFB;
#pragma unroll
        for (int t = 0; t < 4; t++) {
            const int row0 = (t < 2) ? block_row : block_col;
            const __nv_bfloat16* src = srcs[t];
#pragma unroll
            for (int i = 0; i < 4; i++) {
                int idx = i * 256 + tid;
                int r = idx >> 3;
                int c = idx & 7;
                const void* g = src + (size_t)(row0 + r) * NVIS + k0 + c * 8;
                uint32_t d = smem_u32(bufp + t * TILEB + r * ROWB + c * 16);
                CP_ASYNC(d, g);
            }
        }
    };

    const int m_off = (wid >> 2) * 64;
    const int n_off = (wid & 3) * 32;

    const uint32_t a_lane = (uint32_t)(m_off + (lane & 15)) * ROWB + (lane >> 4) * 16;
    const uint32_t b_lane = (uint32_t)(n_off + ((lane >> 4) & 1) * 8 + (lane & 7)) * ROWB
                          + ((lane >> 3) & 1) * 16;

    float acc[4][4][4];
#pragma unroll
    for (int mi = 0; mi < 4; mi++)
#pragma unroll
        for (int ni = 0; ni < 4; ni++)
#pragma unroll
            for (int q = 0; q < 4; q++) acc[mi][ni][q] = 0.0f;

    const int NCHUNK = NVIS / KC;

    load_chunk(0, 0); CP_COMMIT();
    load_chunk(KC, 1); CP_COMMIT();

    for (int ch = 0; ch < NCHUNK; ch++) {
        if (ch + 2 < NCHUNK) { load_chunk((ch + 2) * KC, (ch + 2) % STAGES); CP_COMMIT(); }
        if (ch + 2 < NCHUNK)      { CP_WAIT(2); }
        else if (ch + 1 < NCHUNK) { CP_WAIT(1); }
        else                      { CP_WAIT(0); }
        __syncthreads();

        const char* bufp = smem + (ch % STAGES) * BUFB;
        const uint32_t a_base0 = smem_u32(bufp) + a_lane;
        const uint32_t a_base1 = a_base0 + TILEB;
        const uint32_t b_base0 = smem_u32(bufp + 2 * TILEB) + b_lane;
        const uint32_t b_base1 = b_base0 + TILEB;

#pragma unroll
        for (int ks = 0; ks < KC / 16; ks++) {
            uint32_t Af[2][4][4];
            uint32_t Bf[2][4][2];
#pragma unroll
            for (int mi = 0; mi < 4; mi++) {
                LDSM_X4(Af[0][mi][0], Af[0][mi][1], Af[0][mi][2], Af[0][mi][3],
                        a_base0 + (uint32_t)mi * 16 * ROWB + ks * 32);
                LDSM_X4(Af[1][mi][0], Af[1][mi][1], Af[1][mi][2], Af[1][mi][3],
                        a_base1 + (uint32_t)mi * 16 * ROWB + ks * 32);
            }
#pragma unroll
            for (int g = 0; g < 2; g++) {
                LDSM_X4(Bf[0][2*g][0], Bf[0][2*g][1], Bf[0][2*g+1][0], Bf[0][2*g+1][1],
                        b_base0 + (uint32_t)g * 16 * ROWB + ks * 32);
                LDSM_X4(Bf[1][2*g][0], Bf[1][2*g][1], Bf[1][2*g+1][0], Bf[1][2*g+1][1],
                        b_base1 + (uint32_t)g * 16 * ROWB + ks * 32);
            }
#pragma unroll
            for (int mi = 0; mi < 4; mi++)
#pragma unroll
                for (int ni = 0; ni < 4; ni++) {
                    MMA16816(acc[mi][ni][0], acc[mi][ni][1], acc[mi][ni][2], acc[mi][ni][3],
                             Af[0][mi][0], Af[0][mi][1], Af[0][mi][2], Af[0][mi][3],
                             Bf[0][ni][0], Bf[0][ni][1]);
                    MMA16816(acc[mi][ni][0], acc[mi][ni][1], acc[mi][ni][2], acc[mi][ni][3],
                             Af[0][mi][0], Af[0][mi][1], Af[0][mi][2], Af[0][mi][3],
                             Bf[1][ni][0], Bf[1][ni][1]);
                    MMA16816(acc[mi][ni][0], acc[mi][ni][1], acc[mi][ni][2], acc[mi][ni][3],
                             Af[1][mi][0], Af[1][mi][1], Af[1][mi][2], Af[1][mi][3],
                             Bf[0][ni][0], Bf[0][ni][1]);
                }
        }
        __syncthreads();
    }

#pragma unroll
    for (int mi = 0; mi < 4; mi++) {
        const int r0 = block_row + m_off + mi * 16 + (lane >> 2);
        const int r1 = r0 + 8;
#pragma unroll
        for (int ni = 0; ni < 4; ni++) {
            const int col = block_col + n_off + ni * 8 + (lane & 3) * 2;
            const float c0 = __ldg(cvec + col);
            const float c1 = __ldg(cvec + col + 1);
            float2 o0 = {acc[mi][ni][0] + c0, acc[mi][ni][1] + c1};
            float2 o1 = {acc[mi][ni][2] + c0, acc[mi][ni][3] + c1};
            *(float2*)(g_pre + (size_t)r0 * NHID + col) = o0;
            *(float2*)(g_pre + (size_t)r1 * NHID + col) = o1;
            __nv_bfloat162 m0, m1;
            m0.x = __float2bfloat16(o0.x > 21.0f ? 1.0f : 0.0f);
            m0.y = __float2bfloat16(o0.y > 21.0f ? 1.0f : 0.0f);
            m1.x = __float2bfloat16(o1.x > 21.0f ? 1.0f : 0.0f);
            m1.y = __float2bfloat16(o1.y > 21.0f ? 1.0f : 0.0f);
            *(__nv_bfloat162*)(g_mask + (size_t)r0 * NHID + col) = m0;
            *(__nv_bfloat162*)(g_mask + (size_t)r1 * NHID + col) = m1;
        }
    }
}

// ---------------------------------------------------------------------------
// K2 (FUSED): blocks [0,64): mask-GEMM (single-stage, hidden in occupancy
// slack); blocks [64, 1088): fenergy partials (R13-proven config: 4 j-quarters
// x 256 row-blocks, 8 rows/CTA). One 46.3KB dynamic smem buffer for both.
// ---------------------------------------------------------------------------
#define TJ 128
#define UPAD 133
#define MG_TA   (128 * ROWB)             // 18432
#define MG_TU   (64 * ROWB)              // 9216
#define MG_BUF  (MG_TA + 3 * MG_TU)      // 46080
#define FE_US   (64 * UPAD * 4)          // 34048
#define FE_PS   (8 * TJ * 4)             // 4096
#define FUSED_SMEM 46848                 // max(MG_BUF, 34048+4096+8192) + pad

__global__ __launch_bounds__(256, 4) void fused_fg_kernel(const float* __restrict__ U) {
    extern __shared__ char smem[];
    const int tid  = threadIdx.x;
    const int wid  = tid >> 5;
    const int lane = tid & 31;

    if (blockIdx.x < 64) {
        // ================= mask-GEMM branch =================
        const int k_part    = blockIdx.x & 3;
        const int block_row = (blockIdx.x >> 2) * 128;
        const int k_base    = k_part * 256;

        const __nv_bfloat16* usrc[3] = {g_uh, g_um, g_ul};

        const int m_off = (wid & 3) * 32;
        const int n_off = (wid >> 2) * 32;
        const uint32_t a_lane = (uint32_t)(m_off + (lane & 15)) * ROWB + (lane >> 4) * 16;
        const uint32_t b_lane = (uint32_t)(n_off + ((lane >> 4) & 1) * 8 + (lane & 7)) * ROWB
                              + ((lane >> 3) & 1) * 16;

        float acc[2][4][4];
#pragma unroll
        for (int mi = 0; mi < 2; mi++)
#pragma unroll
            for (int ni = 0; ni < 4; ni++)
#pragma unroll
                for (int q = 0; q < 4; q++) acc[mi][ni][q] = 0.0f;

        for (int ch = 0; ch < 4; ch++) {
            const int k0 = k_base + ch * KC;
            // load M tile (128 x 8 chunks) + 3 U limb tiles (64 x 8 each)
#pragma unroll
            for (int i = 0; i < 4; i++) {
                int idx = i * 256 + tid;
                int r = idx >> 3, c = idx & 7;
                CP_ASYNC(smem_u32(smem + r * ROWB + c * 16),
                         g_mask + (size_t)(block_row + r) * NHID + k0 + c * 8);
            }
#pragma unroll
            for (int t = 0; t < 3; t++) {
#pragma unroll
                for (int i = 0; i < 2; i++) {
                    int idx = i * 256 + tid;
                    int r = idx >> 3, c = idx & 7;
                    CP_ASYNC(smem_u32(smem + MG_TA + t * MG_TU + r * ROWB + c * 16),
                             usrc[t] + (size_t)r * NHID + k0 + c * 8);
                }
            }
            CP_COMMIT(); CP_WAIT(0);
            __syncthreads();

            const uint32_t a_base = smem_u32(smem) + a_lane;
            const uint32_t b_base = smem_u32(smem + MG_TA) + b_lane;

#pragma unroll
            for (int ks = 0; ks < KC / 16; ks++) {
                uint32_t Af[2][4];
#pragma unroll
                for (int mi = 0; mi < 2; mi++)
                    LDSM_X4(Af[mi][0], Af[mi][1], Af[mi][2], Af[mi][3],
                            a_base + (uint32_t)mi * 16 * ROWB + ks * 32);
#pragma unroll
                for (int t = 0; t < 3; t++) {
                    uint32_t Bf[4][2];
#pragma unroll
                    for (int g = 0; g < 2; g++)
                        LDSM_X4(Bf[2*g][0], Bf[2*g][1], Bf[2*g+1][0], Bf[2*g+1][1],
                                b_base + t * MG_TU + (uint32_t)g * 16 * ROWB + ks * 32);
#pragma unroll
                    for (int mi = 0; mi < 2; mi++)
#pragma unroll
                        for (int ni = 0; ni < 4; ni++)
                            MMA16816(acc[mi][ni][0], acc[mi][ni][1], acc[mi][ni][2], acc[mi][ni][3],
                                     Af[mi][0], Af[mi][1], Af[mi][2], Af[mi][3],
                                     Bf[ni][0], Bf[ni][1]);
                }
            }
            __syncthreads();
        }

        float* gout = g_G + (size_t)k_part * B_DIM * NCLASS;
#pragma unroll
        for (int mi = 0; mi < 2; mi++) {
            const int r0 = block_row + m_off + mi * 16 + (lane >> 2);
            const int r1 = r0 + 8;
#pragma unroll
            for (int ni = 0; ni < 4; ni++) {
                const int col = n_off + ni * 8 + (lane & 3) * 2;
                *(float2*)(gout + (size_t)r0 * NCLASS + col) =
                    make_float2(acc[mi][ni][0], acc[mi][ni][1]);
                *(float2*)(gout + (size_t)r1 * NCLASS + col) =
                    make_float2(acc[mi][ni][2], acc[mi][ni][3]);
            }
        }
    } else {
        // ================= fenergy branch (R13 config) =================
        float*  Us    = (float*)smem;                          // 34048 B
        float (*ps)[TJ]     = (float(*)[TJ])(smem + FE_US);    // 4096 B
        float2 (*slist)[TJ] = (float2(*)[TJ])(smem + FE_US + FE_PS); // 8192 B

        const int t    = blockIdx.x - 64;
        const int jq   = t & 3;
        const int b0   = (t >> 2) * 8;
        const int jq0  = jq * 256;
        const int y0   = lane;
        const int y1   = lane + 32;

        const float* urow0 = &Us[y0 * UPAD];
        const float* urow1 = &Us[y1 * UPAD];

        const float LOG2E = 1.4426950408889634f;
        const float LN2   = 0.6931471805599453f;

        float acc0 = 0.0f, acc1 = 0.0f;

#pragma unroll
        for (int jt = 0; jt < 2; jt++) {
            const int j0 = jq0 + jt * TJ;
#pragma unroll
            for (int i = 0; i < 8; i++) {
                int e  = i * 256 + tid;
                int yy = e >> 5;
                int jqq = (e & 31) * 4;
                float4 u4 = *(const float4*)(U + (size_t)yy * NHID + j0 + jqq);
                float* dst = &Us[yy * UPAD + jqq];
                dst[0] = u4.x; dst[1] = u4.y; dst[2] = u4.z; dst[3] = u4.w;
            }
            {
                int bb = tid >> 5;
                int jqq = (tid & 31) * 4;
                float4 p4 = *(const float4*)(g_pre + (size_t)(b0 + bb) * NHID + j0 + jqq);
                *(float4*)&ps[bb][jqq] = p4;
            }
            __syncthreads();

            int cnt = 0;
#pragma unroll
            for (int s = 0; s < 4; s++) {
                int jj = s * 32 + lane;
                float p = ps[wid][jj];
                bool slow = fabsf(p) <= 21.0f;
                unsigned mask = __ballot_sync(0xffffffffu, slow);
                int rank = __popc(mask & ((1u << lane) - 1u));
                if (slow) slist[wid][cnt + rank] = make_float2(__int_as_float(jj), p);
                cnt += __popc(mask);
            }

            float a0 = 0.f, a1 = 0.f;
            float c0 = 0.f, c1 = 0.f;
            float P0 = 1.f, P1 = 1.f;
            for (int i = 0; i < cnt; i++) {
                float2 e = slist[wid][i];
                int jj  = __float_as_int(e.x);
                float p = e.y;
                float x0 = p + urow0[jj];
                float x1 = p + urow1[jj];
                a0 += fmaxf(x0, 0.f);
                a1 += fmaxf(x1, 0.f);
                P0 = fmaf(P0, exp2f(-fabsf(x0) * LOG2E), P0);
                P1 = fmaf(P1, exp2f(-fabsf(x1) * LOG2E), P1);
                if ((i & 31) == 31) {
                    c0 += __log2f(P0); P0 = 1.f;
                    c1 += __log2f(P1); P1 = 1.f;
                }
            }
            c0 += __log2f(P0);
            c1 += __log2f(P1);

            acc0 += a0 + LN2 * c0;
            acc1 += a1 + LN2 * c1;
            __syncthreads();
        }

        const int b = b0 + wid;
        float* fp = g_Fp + (size_t)jq * B_DIM * NCLASS + (size_t)b * NCLASS;
        fp[y0] = acc0;
        fp[y1] = acc1;
    }
}

// ---------------------------------------------------------------------------
// K3: combine partials + softmax + argmax + one_hot. Warp = batch row.
// ---------------------------------------------------------------------------
__global__ __launch_bounds__(256) void combine_kernel(const float* __restrict__ dvec,
                                                      float* __restrict__ out) {
    const int wid  = threadIdx.x >> 5;
    const int lane = threadIdx.x & 31;
    const int b    = blockIdx.x * 8 + wid;
    const int y0   = lane;
    const int y1   = lane + 32;

    float f0 = __ldg(dvec + y0);
    float f1 = __ldg(dvec + y1);
#pragma unroll
    for (int q = 0; q < 4; q++) {
        const size_t off = (size_t)q * B_DIM * NCLASS + (size_t)b * NCLASS;
        f0 += g_G[off + y0] + g_Fp[off + y0];
        f1 += g_G[off + y1] + g_Fp[off + y1];
    }

    float m = fmaxf(f0, f1);
#pragma unroll
    for (int o = 16; o > 0; o >>= 1) m = fmaxf(m, __shfl_xor_sync(0xffffffffu, m, o));
    float e0 = __expf(f0 - m);
    float e1 = __expf(f1 - m);
    float s = e0 + e1;
#pragma unroll
    for (int o = 16; o > 0; o >>= 1) s += __shfl_xor_sync(0xffffffffu, s, o);
    float inv = 1.0f / s;
    float p0 = e0 * inv;
    float p1 = e1 * inv;

    float pm = p0; int im = y0;
    if (p1 > pm) { pm = p1; im = y1; }
#pragma unroll
    for (int o = 16; o > 0; o >>= 1) {
        float po = __shfl_xor_sync(0xffffffffu, pm, o);
        int   io = __shfl_xor_sync(0xffffffffu, im, o);
        if (po > pm || (po == pm && io < im)) { pm = po; im = io; }
    }

    out[(size_t)b * NCLASS + y0] = p0;
    out[(size_t)b * NCLASS + y1] = p1;
    float* oh = out + (size_t)B_DIM * NCLASS;
    oh[(size_t)b * NCLASS + y0] = (y0 == im) ? 1.0f : 0.0f;
    oh[(size_t)b * NCLASS + y1] = (y1 == im) ? 1.0f : 0.0f;
}

// ---------------------------------------------------------------------------
extern "C" void kernel_launch(void* const* d_in, const int* in_sizes, int n_in,
                              void* d_out, int out_size) {
    const float* v = (const float*)d_in[0];
    const float* W = (const float*)d_in[1];
    const float* c = (const float*)d_in[2];
    const float* d = (const float*)d_in[3];
    const float* U = (const float*)d_in[4];
    float* out = (float*)d_out;

    cudaFuncSetAttribute(gemm_mma_kernel,
                         cudaFuncAttributeMaxDynamicSharedMemorySize, GEMM_SMEM);
    cudaFuncSetAttribute(fused_fg_kernel,
                         cudaFuncAttributeMaxDynamicSharedMemorySize, FUSED_SMEM);

    split_kernel<<<3088, 256>>>(v, W, U);
    gemm_mma_kernel<<<dim3(NHID / 128, B_DIM / 128), 256, GEMM_SMEM>>>(c);
    fused_fg_kernel<<<64 + 4 * (B_DIM / 8), 256, FUSED_SMEM>>>(U);
    combine_kernel<<<B_DIM / 8, 256>>>(d, out);
}

// round 17
// speedup vs baseline: 1.0831x; 1.0010x over previous
#include <cuda_runtime.h>
#include <cuda_bf16.h>
#include <cstdint>

#define B_DIM  2048
#define NVIS   2048
#define NHID   1024
#define NCLASS 64

// ---------------------------------------------------------------------------
// Static device scratch
// ---------------------------------------------------------------------------
__device__ float g_pre[B_DIM * NHID];                 // 8 MB
__device__ __nv_bfloat16 g_vh[B_DIM * NVIS];          // 8 MB
__device__ __nv_bfloat16 g_vm[B_DIM * NVIS];          // 8 MB
__device__ __nv_bfloat16 g_wh[NHID * NVIS];           // 4 MB (W^T limbs, [n][k])
__device__ __nv_bfloat16 g_wm[NHID * NVIS];           // 4 MB
__device__ __nv_bfloat16 g_mask[B_DIM * NHID];        // 4 MB  M[b][j] = 1[p>21]
__device__ __nv_bfloat16 g_uh[NCLASS * NHID];         // U limbs [y][j]
__device__ __nv_bfloat16 g_um[NCLASS * NHID];
__device__ __nv_bfloat16 g_ul[NCLASS * NHID];
__device__ float g_G[4 * B_DIM * NCLASS];             // 2 MB  split-K mask-GEMM parts
__device__ float g_Fp[4 * B_DIM * NCLASS];            // 2 MB  split-j fenergy partials

__device__ __forceinline__ uint32_t smem_u32(const void* p) {
    uint32_t a;
    asm("{ .reg .u64 t; cvta.to.shared.u64 t, %1; cvt.u32.u64 %0, t; }" : "=r"(a) : "l"(p));
    return a;
}

// ---------------------------------------------------------------------------
// K0: fused split kernel: v limbs, W^T limbs, U 3-limb copies
// ---------------------------------------------------------------------------
__global__ __launch_bounds__(256) void split_kernel(const float* __restrict__ v,
                                                    const float* __restrict__ W,
                                                    const float* __restrict__ U) {
    if (blockIdx.x < 1024) {
        const int base = blockIdx.x * 1024 + threadIdx.x;   // float4 index
        float4 x[4];
#pragma unroll
        for (int r = 0; r < 4; r++)
            x[r] = *(const float4*)(v + (size_t)(base + r * 256) * 4);
#pragma unroll
        for (int r = 0; r < 4; r++) {
            float xs[4] = {x[r].x, x[r].y, x[r].z, x[r].w};
            __nv_bfloat16 hb[4], mb[4];
#pragma unroll
            for (int i = 0; i < 4; i++) {
                hb[i] = __float2bfloat16(xs[i]);
                mb[i] = __float2bfloat16(xs[i] - __bfloat162float(hb[i]));
            }
            size_t o = (size_t)(base + r * 256) * 4;
            *(uint2*)(g_vh + o) = *(uint2*)hb;
            *(uint2*)(g_vm + o) = *(uint2*)mb;
        }
    } else if (blockIdx.x < 3072) {
        __shared__ float s[32][33];
        int bid = blockIdx.x - 1024;
        int nb = (bid & 31) * 32;
        int kb = (bid >> 5) * 32;
        int tx = threadIdx.x & 31;
        int ty = threadIdx.x >> 5;
        float w[4];
#pragma unroll
        for (int i = 0; i < 4; i++)
            w[i] = W[(size_t)(kb + ty + i * 8) * NHID + nb + tx];
#pragma unroll
        for (int i = 0; i < 4; i++)
            s[ty + i * 8][tx] = w[i];
        __syncthreads();
#pragma unroll
        for (int i = 0; i < 4; i++) {
            int n = ty + i * 8;
            float x = s[tx][n];
            __nv_bfloat16 h = __float2bfloat16(x);
            __nv_bfloat16 m = __float2bfloat16(x - __bfloat162float(h));
            size_t o = (size_t)(nb + n) * NVIS + kb + tx;
            g_wh[o] = h; g_wm[o] = m;
        }
    } else {
        // U 3-limb split: 16 blocks x 256 threads x 4 float4 = 65536 elems
        const int base = (blockIdx.x - 3072) * 1024 + threadIdx.x;
#pragma unroll
        for (int r = 0; r < 4; r++) {
            int idx = base + r * 256;
            float4 x4 = *(const float4*)(U + (size_t)idx * 4);
            float xs[4] = {x4.x, x4.y, x4.z, x4.w};
            __nv_bfloat16 hb[4], mb[4], lb[4];
#pragma unroll
            for (int i = 0; i < 4; i++) {
                hb[i] = __float2bfloat16(xs[i]);
                float r1 = xs[i] - __bfloat162float(hb[i]);
                mb[i] = __float2bfloat16(r1);
                lb[i] = __float2bfloat16(r1 - __bfloat162float(mb[i]));
            }
            size_t o = (size_t)idx * 4;
            *(uint2*)(g_uh + o) = *(uint2*)hb;
            *(uint2*)(g_um + o) = *(uint2*)mb;
            *(uint2*)(g_ul + o) = *(uint2*)lb;
        }
    }
}

// ---------------------------------------------------------------------------
// Shared GEMM macros
// ---------------------------------------------------------------------------
#define CP_ASYNC(dst, src) \
    asm volatile("cp.async.cg.shared.global [%0], [%1], 16;" :: "r"(dst), "l"(src))
#define CP_COMMIT() asm volatile("cp.async.commit_group;" ::: "memory")
#define CP_WAIT(n)  asm volatile("cp.async.wait_group %0;" :: "n"(n) : "memory")

#define LDSM_X4(r0, r1, r2, r3, a) \
    asm volatile("ldmatrix.sync.aligned.m8n8.x4.shared.b16 {%0,%1,%2,%3}, [%4];" \
        : "=r"(r0), "=r"(r1), "=r"(r2), "=r"(r3) : "r"(a))

#define MMA16816(c0, c1, c2, c3, a0, a1, a2, a3, b0, b1) \
    asm volatile("mma.sync.aligned.m16n8k16.row.col.f32.bf16.bf16.f32 " \
        "{%0,%1,%2,%3}, {%4,%5,%6,%7}, {%8,%9}, {%0,%1,%2,%3};" \
        : "+f"(c0), "+f"(c1), "+f"(c2), "+f"(c3) \
        : "r"(a0), "r"(a1), "r"(a2), "r"(a3), "r"(b0), "r"(b1))

// ---------------------------------------------------------------------------
// K1: pre = v @ W + c  (proven config) + mask write in epilogue
// ---------------------------------------------------------------------------
#define KC        64
#define ROWB      144
#define TILEB     (128 * ROWB)
#define BUFB      (4 * TILEB)
#define STAGES    3
#define GEMM_SMEM (STAGES * BUFB)        // 221184

__global__ __launch_bounds__(256, 1) void gemm_mma_kernel(const float* __restrict__ cvec) {
    extern __shared__ char smem[];
    const int tid  = threadIdx.x;
    const int wid  = tid >> 5;
    const int lane = tid & 31;
    const int block_row = blockIdx.y * 128;
    const int block_col = blockIdx.x * 128;

    const __nv_bfloat16* srcs[4] = {g_vh, g_vm, g_wh, g_wm};

    auto load_chunk = [&](int k0, int stage) {
        char* bufp = smem + stage * BUFB;
#pragma unroll
        for (int t = 0; t < 4; t++) {
            const int row0 = (t < 2) ? block_row : block_col;
            const __nv_bfloat16* src = srcs[t];
#pragma unroll
            for (int i = 0; i < 4; i++) {
                int idx = i * 256 + tid;
                int r = idx >> 3;
                int c = idx & 7;
                const void* g = src + (size_t)(row0 + r) * NVIS + k0 + c * 8;
                uint32_t d = smem_u32(bufp + t * TILEB + r * ROWB + c * 16);
                CP_ASYNC(d, g);
            }
        }
    };

    const int m_off = (wid >> 2) * 64;
    const int n_off = (wid & 3) * 32;

    const uint32_t a_lane = (uint32_t)(m_off + (lane & 15)) * ROWB + (lane >> 4) * 16;
    const uint32_t b_lane = (uint32_t)(n_off + ((lane >> 4) & 1) * 8 + (lane & 7)) * ROWB
                          + ((lane >> 3) & 1) * 16;

    float acc[4][4][4];
#pragma unroll
    for (int mi = 0; mi < 4; mi++)
#pragma unroll
        for (int ni = 0; ni < 4; ni++)
#pragma unroll
            for (int q = 0; q < 4; q++) acc[mi][ni][q] = 0.0f;

    const int NCHUNK = NVIS / KC;

    load_chunk(0, 0); CP_COMMIT();
    load_chunk(KC, 1); CP_COMMIT();

    for (int ch = 0; ch < NCHUNK; ch++) {
        if (ch + 2 < NCHUNK) { load_chunk((ch + 2) * KC, (ch + 2) % STAGES); CP_COMMIT(); }
        if (ch + 2 < NCHUNK)      { CP_WAIT(2); }
        else if (ch + 1 < NCHUNK) { CP_WAIT(1); }
        else                      { CP_WAIT(0); }
        __syncthreads();

        const char* bufp = smem + (ch % STAGES) * BUFB;
        const uint32_t a_base0 = smem_u32(bufp) + a_lane;
        const uint32_t a_base1 = a_base0 + TILEB;
        const uint32_t b_base0 = smem_u32(bufp + 2 * TILEB) + b_lane;
        const uint32_t b_base1 = b_base0 + TILEB;

#pragma unroll
        for (int ks = 0; ks < KC / 16; ks++) {
            uint32_t Af[2][4][4];
            uint32_t Bf[2][4][2];
#pragma unroll
            for (int mi = 0; mi < 4; mi++) {
                LDSM_X4(Af[0][mi][0], Af[0][mi][1], Af[0][mi][2], Af[0][mi][3],
                        a_base0 + (uint32_t)mi * 16 * ROWB + ks * 32);
                LDSM_X4(Af[1][mi][0], Af[1][mi][1], Af[1][mi][2], Af[1][mi][3],
                        a_base1 + (uint32_t)mi * 16 * ROWB + ks * 32);
            }
#pragma unroll
            for (int g = 0; g < 2; g++) {
                LDSM_X4(Bf[0][2*g][0], Bf[0][2*g][1], Bf[0][2*g+1][0], Bf[0][2*g+1][1],
                        b_base0 + (uint32_t)g * 16 * ROWB + ks * 32);
                LDSM_X4(Bf[1][2*g][0], Bf[1][2*g][1], Bf[1][2*g+1][0], Bf[1][2*g+1][1],
                        b_base1 + (uint32_t)g * 16 * ROWB + ks * 32);
            }
#pragma unroll
            for (int mi = 0; mi < 4; mi++)
#pragma unroll
                for (int ni = 0; ni < 4; ni++) {
                    MMA16816(acc[mi][ni][0], acc[mi][ni][1], acc[mi][ni][2], acc[mi][ni][3],
                             Af[0][mi][0], Af[0][mi][1], Af[0][mi][2], Af[0][mi][3],
                             Bf[0][ni][0], Bf[0][ni][1]);
                    MMA16816(acc[mi][ni][0], acc[mi][ni][1], acc[mi][ni][2], acc[mi][ni][3],
                             Af[0][mi][0], Af[0][mi][1], Af[0][mi][2], Af[0][mi][3],
                             Bf[1][ni][0], Bf[1][ni][1]);
                    MMA16816(acc[mi][ni][0], acc[mi][ni][1], acc[mi][ni][2], acc[mi][ni][3],
                             Af[1][mi][0], Af[1][mi][1], Af[1][mi][2], Af[1][mi][3],
                             Bf[0][ni][0], Bf[0][ni][1]);
                }
        }
        __syncthreads();
    }

#pragma unroll
    for (int mi = 0; mi < 4; mi++) {
        const int r0 = block_row + m_off + mi * 16 + (lane >> 2);
        const int r1 = r0 + 8;
#pragma unroll
        for (int ni = 0; ni < 4; ni++) {
            const int col = block_col + n_off + ni * 8 + (lane & 3) * 2;
            const float c0 = __ldg(cvec + col);
            const float c1 = __ldg(cvec + col + 1);
            float2 o0 = {acc[mi][ni][0] + c0, acc[mi][ni][1] + c1};
            float2 o1 = {acc[mi][ni][2] + c0, acc[mi][ni][3] + c1};
            *(float2*)(g_pre + (size_t)r0 * NHID + col) = o0;
            *(float2*)(g_pre + (size_t)r1 * NHID + col) = o1;
            __nv_bfloat162 m0, m1;
            m0.x = __float2bfloat16(o0.x > 21.0f ? 1.0f : 0.0f);
            m0.y = __float2bfloat16(o0.y > 21.0f ? 1.0f : 0.0f);
            m1.x = __float2bfloat16(o1.x > 21.0f ? 1.0f : 0.0f);
            m1.y = __float2bfloat16(o1.y > 21.0f ? 1.0f : 0.0f);
            *(__nv_bfloat162*)(g_mask + (size_t)r0 * NHID + col) = m0;
            *(__nv_bfloat162*)(g_mask + (size_t)r1 * NHID + col) = m1;
        }
    }
}

// ---------------------------------------------------------------------------
// K2 (FUSED): blocks [0,64): mask-GEMM (single-stage, hidden in occupancy
// slack); blocks [64, 1088): fenergy partials (R13-proven config: 4 j-quarters
// x 256 row-blocks, 8 rows/CTA). One 46.3KB dynamic smem buffer for both.
// ---------------------------------------------------------------------------
#define TJ 128
#define UPAD 133
#define MG_TA   (128 * ROWB)             // 18432
#define MG_TU   (64 * ROWB)              // 9216
#define MG_BUF  (MG_TA + 3 * MG_TU)      // 46080
#define FE_US   (64 * UPAD * 4)          // 34048
#define FE_PS   (8 * TJ * 4)             // 4096
#define FUSED_SMEM 46848                 // max(MG_BUF, 34048+4096+8192) + pad

__global__ __launch_bounds__(256, 4) void fused_fg_kernel(const float* __restrict__ U) {
    extern __shared__ char smem[];
    const int tid  = threadIdx.x;
    const int wid  = tid >> 5;
    const int lane = tid & 31;

    if (blockIdx.x < 64) {
        // ================= mask-GEMM branch =================
        const int k_part    = blockIdx.x & 3;
        const int block_row = (blockIdx.x >> 2) * 128;
        const int k_base    = k_part * 256;

        const __nv_bfloat16* usrc[3] = {g_uh, g_um, g_ul};

        const int m_off = (wid & 3) * 32;
        const int n_off = (wid >> 2) * 32;
        const uint32_t a_lane = (uint32_t)(m_off + (lane & 15)) * ROWB + (lane >> 4) * 16;
        const uint32_t b_lane = (uint32_t)(n_off + ((lane >> 4) & 1) * 8 + (lane & 7)) * ROWB
                              + ((lane >> 3) & 1) * 16;

        float acc[2][4][4];
#pragma unroll
        for (int mi = 0; mi < 2; mi++)
#pragma unroll
            for (int ni = 0; ni < 4; ni++)
#pragma unroll
                for (int q = 0; q < 4; q++) acc[mi][ni][q] = 0.0f;

        for (int ch = 0; ch < 4; ch++) {
            const int k0 = k_base + ch * KC;
            // load M tile (128 x 8 chunks) + 3 U limb tiles (64 x 8 each)
#pragma unroll
            for (int i = 0; i < 4; i++) {
                int idx = i * 256 + tid;
                int r = idx >> 3, c = idx & 7;
                CP_ASYNC(smem_u32(smem + r * ROWB + c * 16),
                         g_mask + (size_t)(block_row + r) * NHID + k0 + c * 8);
            }
#pragma unroll
            for (int t = 0; t < 3; t++) {
#pragma unroll
                for (int i = 0; i < 2; i++) {
                    int idx = i * 256 + tid;
                    int r = idx >> 3, c = idx & 7;
                    CP_ASYNC(smem_u32(smem + MG_TA + t * MG_TU + r * ROWB + c * 16),
                             usrc[t] + (size_t)r * NHID + k0 + c * 8);
                }
            }
            CP_COMMIT(); CP_WAIT(0);
            __syncthreads();

            const uint32_t a_base = smem_u32(smem) + a_lane;
            const uint32_t b_base = smem_u32(smem + MG_TA) + b_lane;

#pragma unroll
            for (int ks = 0; ks < KC / 16; ks++) {
                uint32_t Af[2][4];
#pragma unroll
                for (int mi = 0; mi < 2; mi++)
                    LDSM_X4(Af[mi][0], Af[mi][1], Af[mi][2], Af[mi][3],
                            a_base + (uint32_t)mi * 16 * ROWB + ks * 32);
#pragma unroll
                for (int t = 0; t < 3; t++) {
                    uint32_t Bf[4][2];
#pragma unroll
                    for (int g = 0; g < 2; g++)
                        LDSM_X4(Bf[2*g][0], Bf[2*g][1], Bf[2*g+1][0], Bf[2*g+1][1],
                                b_base + t * MG_TU + (uint32_t)g * 16 * ROWB + ks * 32);
#pragma unroll
                    for (int mi = 0; mi < 2; mi++)
#pragma unroll
                        for (int ni = 0; ni < 4; ni++)
                            MMA16816(acc[mi][ni][0], acc[mi][ni][1], acc[mi][ni][2], acc[mi][ni][3],
                                     Af[mi][0], Af[mi][1], Af[mi][2], Af[mi][3],
                                     Bf[ni][0], Bf[ni][1]);
                }
            }
            __syncthreads();
        }

        float* gout = g_G + (size_t)k_part * B_DIM * NCLASS;
#pragma unroll
        for (int mi = 0; mi < 2; mi++) {
            const int r0 = block_row + m_off + mi * 16 + (lane >> 2);
            const int r1 = r0 + 8;
#pragma unroll
            for (int ni = 0; ni < 4; ni++) {
                const int col = n_off + ni * 8 + (lane & 3) * 2;
                *(float2*)(gout + (size_t)r0 * NCLASS + col) =
                    make_float2(acc[mi][ni][0], acc[mi][ni][1]);
                *(float2*)(gout + (size_t)r1 * NCLASS + col) =
                    make_float2(acc[mi][ni][2], acc[mi][ni][3]);
            }
        }
    } else {
        // ================= fenergy branch (R13 config) =================
        float*  Us    = (float*)smem;                          // 34048 B
        float (*ps)[TJ]     = (float(*)[TJ])(smem + FE_US);    // 4096 B
        float2 (*slist)[TJ] = (float2(*)[TJ])(smem + FE_US + FE_PS); // 8192 B

        const int t    = blockIdx.x - 64;
        const int jq   = t & 3;
        const int b0   = (t >> 2) * 8;
        const int jq0  = jq * 256;
        const int y0   = lane;
        const int y1   = lane + 32;

        const float* urow0 = &Us[y0 * UPAD];
        const float* urow1 = &Us[y1 * UPAD];

        const float LOG2E = 1.4426950408889634f;
        const float LN2   = 0.6931471805599453f;

        float acc0 = 0.0f, acc1 = 0.0f;

#pragma unroll
        for (int jt = 0; jt < 2; jt++) {
            const int j0 = jq0 + jt * TJ;
#pragma unroll
            for (int i = 0; i < 8; i++) {
                int e  = i * 256 + tid;
                int yy = e >> 5;
                int jqq = (e & 31) * 4;
                float4 u4 = *(const float4*)(U + (size_t)yy * NHID + j0 + jqq);
                float* dst = &Us[yy * UPAD + jqq];
                dst[0] = u4.x; dst[1] = u4.y; dst[2] = u4.z; dst[3] = u4.w;
            }
            {
                int bb = tid >> 5;
                int jqq = (tid & 31) * 4;
                float4 p4 = *(const float4*)(g_pre + (size_t)(b0 + bb) * NHID + j0 + jqq);
                *(float4*)&ps[bb][jqq] = p4;
            }
            __syncthreads();

            int cnt = 0;
#pragma unroll
            for (int s = 0; s < 4; s++) {
                int jj = s * 32 + lane;
                float p = ps[wid][jj];
                bool slow = fabsf(p) <= 21.0f;
                unsigned mask = __ballot_sync(0xffffffffu, slow);
                int rank = __popc(mask & ((1u << lane) - 1u));
                if (slow) slist[wid][cnt + rank] = make_float2(__int_as_float(jj), p);
                cnt += __popc(mask);
            }

            float a0 = 0.f, a1 = 0.f;
            float c0 = 0.f, c1 = 0.f;
            float P0 = 1.f, P1 = 1.f;
            for (int i = 0; i < cnt; i++) {
                float2 e = slist[wid][i];
                int jj  = __float_as_int(e.x);
                float p = e.y;
                float x0 = p + urow0[jj];
                float x1 = p + urow1[jj];
                a0 += fmaxf(x0, 0.f);
                a1 += fmaxf(x1, 0.f);
                P0 = fmaf(P0, exp2f(-fabsf(x0) * LOG2E), P0);
                P1 = fmaf(P1, exp2f(-fabsf(x1) * LOG2E), P1);
                if ((i & 31) == 31) {
                    c0 += __log2f(P0); P0 = 1.f;
                    c1 += __log2f(P1); P1 = 1.f;
                }
            }
            c0 += __log2f(P0);
            c1 += __log2f(P1);

            acc0 += a0 + LN2 * c0;
            acc1 += a1 + LN2 * c1;
            __syncthreads();
        }

        const int b = b0 + wid;
        float* fp = g_Fp + (size_t)jq * B_DIM * NCLASS + (size_t)b * NCLASS;
        fp[y0] = acc0;
        fp[y1] = acc1;
    }
}

// ---------------------------------------------------------------------------
// K3: combine partials + softmax + argmax + one_hot. Warp = batch row.
// ---------------------------------------------------------------------------
__global__ __launch_bounds__(256) void combine_kernel(const float* __restrict__ dvec,
                                                      float* __restrict__ out) {
    const int wid  = threadIdx.x >> 5;
    const int lane = threadIdx.x & 31;
    const int b    = blockIdx.x * 8 + wid;
    const int y0   = lane;
    const int y1   = lane + 32;

    float f0 = __ldg(dvec + y0);
    float f1 = __ldg(dvec + y1);
#pragma unroll
    for (int q = 0; q < 4; q++) {
        const size_t off = (size_t)q * B_DIM * NCLASS + (size_t)b * NCLASS;
        f0 += g_G[off + y0] + g_Fp[off + y0];
        f1 += g_G[off + y1] + g_Fp[off + y1];
    }

    float m = fmaxf(f0, f1);
#pragma unroll
    for (int o = 16; o > 0; o >>= 1) m = fmaxf(m, __shfl_xor_sync(0xffffffffu, m, o));
    float e0 = __expf(f0 - m);
    float e1 = __expf(f1 - m);
    float s = e0 + e1;
#pragma unroll
    for (int o = 16; o > 0; o >>= 1) s += __shfl_xor_sync(0xffffffffu, s, o);
    float inv = 1.0f / s;
    float p0 = e0 * inv;
    float p1 = e1 * inv;

    float pm = p0; int im = y0;
    if (p1 > pm) { pm = p1; im = y1; }
#pragma unroll
    for (int o = 16; o > 0; o >>= 1) {
        float po = __shfl_xor_sync(0xffffffffu, pm, o);
        int   io = __shfl_xor_sync(0xffffffffu, im, o);
        if (po > pm || (po == pm && io < im)) { pm = po; im = io; }
    }

    out[(size_t)b * NCLASS + y0] = p0;
    out[(size_t)b * NCLASS + y1] = p1;
    float* oh = out + (size_t)B_DIM * NCLASS;
    oh[(size_t)b * NCLASS + y0] = (y0 == im) ? 1.0f : 0.0f;
    oh[(size_t)b * NCLASS + y1] = (y1 == im) ? 1.0f : 0.0f;
}

// ---------------------------------------------------------------------------
extern "C" void kernel_launch(void* const* d_in, const int* in_sizes, int n_in,
                              void* d_out, int out_size) {
    const float* v = (const float*)d_in[0];
    const float* W = (const float*)d_in[1];
    const float* c = (const float*)d_in[2];
    const float* d = (const float*)d_in[3];
    const float* U = (const float*)d_in[4];
    float* out = (float*)d_out;

    cudaFuncSetAttribute(gemm_mma_kernel,
                         cudaFuncAttributeMaxDynamicSharedMemorySize, GEMM_SMEM);
    cudaFuncSetAttribute(fused_fg_kernel,
                         cudaFuncAttributeMaxDynamicSharedMemorySize, FUSED_SMEM);

    split_kernel<<<3088, 256>>>(v, W, U);
    gemm_mma_kernel<<<dim3(NHID / 128, B_DIM / 128), 256, GEMM_SMEM>>>(c);
    fused_fg_kernel<<<64 + 4 * (B_DIM / 8), 256, FUSED_SMEM>>>(U);
    combine_kernel<<<B_DIM / 8, 256>>>(d, out);
}